// round 11
// baseline (speedup 1.0000x reference)
#include <cuda_runtime.h>
#include <cuda_bf16.h>
#include <cstdint>

#define NN 50000
#define NE 800000
#define D  128
#define SCAN_B 256
#define TM 128

#define LDS_STRIDE_B 144
#define AHI_OFF 0
#define ALO_OFF 18432
#define BHI_OFF 36864
#define BLO_OFF 55296
#define SM_TOTAL 73728

#define DEG_SCALE 4194304.0f

// ---------------- scratch (static device globals; no allocation) -------------
__device__ float g_h  [NN * D];
__device__ float g_out[NN * D];
__device__ int   g_src [NE];
__device__ int   g_dst [NE];
__device__ int   g_eidx[NE];
__device__ unsigned long long g_pack[NN];
__device__ float g_dinv[NN];
// CSR (by dst)
__device__ int   g_rowtmp[NN];
__device__ int   g_rowptr[NN + 1];
__device__ int   g_bsum  [SCAN_B];
__device__ int   g_boff  [SCAN_B];
__device__ int2  g_csr   [NE];               // .x = src, .y = bitcast(norm)
// pre-split transposed weights
__device__ unsigned short g_whi[4 * 16384];
__device__ unsigned short g_wlo[4 * 16384];

// ---------------- helpers ------------------------------------------------------
__device__ __forceinline__ uint32_t smem_u32(const void* p) {
    uint32_t a;
    asm("{ .reg .u64 t; cvta.to.shared.u64 t, %1; cvt.u32.u64 %0, t; }" : "=r"(a) : "l"(p));
    return a;
}

__device__ __forceinline__ void ldmx4(uint32_t& r0, uint32_t& r1, uint32_t& r2,
                                      uint32_t& r3, uint32_t addr) {
    asm volatile("ldmatrix.sync.aligned.m8n8.x4.shared.b16 {%0,%1,%2,%3}, [%4];"
                 : "=r"(r0), "=r"(r1), "=r"(r2), "=r"(r3) : "r"(addr));
}

__device__ __forceinline__ void mma_bf16(float& c0, float& c1, float& c2, float& c3,
                                         uint32_t a0, uint32_t a1, uint32_t a2, uint32_t a3,
                                         uint32_t b0, uint32_t b1) {
    asm volatile("mma.sync.aligned.m16n8k16.row.col.f32.bf16.bf16.f32 "
                 "{%0,%1,%2,%3}, {%4,%5,%6,%7}, {%8,%9}, {%0,%1,%2,%3};"
                 : "+f"(c0), "+f"(c1), "+f"(c2), "+f"(c3)
                 : "r"(a0), "r"(a1), "r"(a2), "r"(a3), "r"(b0), "r"(b1));
}

__device__ __forceinline__ void split2(float x, float y, uint32_t& hi, uint32_t& lo) {
    __nv_bfloat16 hx = __float2bfloat16(x), hy = __float2bfloat16(y);
    __nv_bfloat16 lx = __float2bfloat16(x - __bfloat162float(hx));
    __nv_bfloat16 ly = __float2bfloat16(y - __bfloat162float(hy));
    hi = (uint32_t)__bfloat16_as_ushort(hx) | ((uint32_t)__bfloat16_as_ushort(hy) << 16);
    lo = (uint32_t)__bfloat16_as_ushort(lx) | ((uint32_t)__bfloat16_as_ushort(ly) << 16);
}

// ---------------- weight pre-split (side stream; no edge deps) ----------------
__global__ void k_wsplit(const float* __restrict__ W0, const float* __restrict__ W1,
                         const float* __restrict__ W2, const float* __restrict__ W3) {
    __shared__ float tile[32][33];
    const int b  = blockIdx.x;
    const int w  = b >> 4;
    const int k0 = ((b >> 2) & 3) * 32;
    const int n0 = (b & 3) * 32;
    const float* W = (w == 0) ? W0 : (w == 1) ? W1 : (w == 2) ? W2 : W3;
    const int tx = threadIdx.x, ty = threadIdx.y;
#pragma unroll
    for (int i = 0; i < 4; i++)
        tile[ty + 8 * i][tx] = W[(size_t)(k0 + ty + 8 * i) * D + n0 + tx];
    __syncthreads();
#pragma unroll
    for (int i = 0; i < 4; i++) {
        float v = tile[tx][ty + 8 * i];
        __nv_bfloat16 h = __float2bfloat16(v);
        __nv_bfloat16 l = __float2bfloat16(v - __bfloat162float(h));
        size_t idx = (size_t)w * 16384 + (size_t)(n0 + ty + 8 * i) * D + k0 + tx;
        g_whi[idx] = __bfloat16_as_ushort(h);
        g_wlo[idx] = __bfloat16_as_ushort(l);
    }
}

// ---------------- tensor-core GEMM (row range [r0base, nlim)) -----------------
template <bool RELU, bool BIAS>
__global__ void __launch_bounds__(256)
k_tgemm(const float* __restrict__ in, const unsigned short* __restrict__ whi,
        const unsigned short* __restrict__ wlo,
        const float* __restrict__ bias, float* __restrict__ out,
        int r0base, int nlim) {
    extern __shared__ char smem[];
    const uint32_t sb  = smem_u32(smem);
    const int tid   = threadIdx.x;
    const int wid   = tid >> 5;
    const int lane  = tid & 31;
    const int rbase = r0base + blockIdx.x * TM;
    const int n     = nlim;

    const int m0 = wid * 16;
    const int rowInA = (lane & 7) + ((lane >> 3) & 1) * 8;
    const int kAddA  = (lane >> 4) * 8;
    const uint32_t aOffBytes = (uint32_t)((m0 + rowInA) * LDS_STRIDE_B + kAddA * 2);
    const int rowInB = (lane & 7) + (lane >> 4) * 8;
    const int kAddB  = ((lane >> 3) & 1) * 8;
    const uint32_t bOffBytes = (uint32_t)(rowInB * LDS_STRIDE_B + kAddB * 2);

    float acc[16][4];
#pragma unroll
    for (int t = 0; t < 16; t++) {
        acc[t][0] = 0.f; acc[t][1] = 0.f; acc[t][2] = 0.f; acc[t][3] = 0.f;
    }

    const int fillRow = tid >> 1;
    const int fillSub = (tid & 1) * 32;

#pragma unroll
    for (int stage = 0; stage < 2; stage++) {
        const int kstage = stage * 64;
        {
            const int r = rbase + fillRow;
            const float4* src = (const float4*)(in + (size_t)r * D + kstage + fillSub);
            char* ah = smem + AHI_OFF + fillRow * LDS_STRIDE_B + fillSub * 2;
            char* al = smem + ALO_OFF + fillRow * LDS_STRIDE_B + fillSub * 2;
#pragma unroll
            for (int k4 = 0; k4 < 8; k4++) {
                float4 v = (r < n) ? src[k4] : make_float4(0.f, 0.f, 0.f, 0.f);
                if (RELU) {
                    v.x = fmaxf(v.x, 0.f); v.y = fmaxf(v.y, 0.f);
                    v.z = fmaxf(v.z, 0.f); v.w = fmaxf(v.w, 0.f);
                }
                uint32_t h01, l01, h23, l23;
                split2(v.x, v.y, h01, l01);
                split2(v.z, v.w, h23, l23);
                *(uint32_t*)(ah + k4 * 8)     = h01;
                *(uint32_t*)(ah + k4 * 8 + 4) = h23;
                *(uint32_t*)(al + k4 * 8)     = l01;
                *(uint32_t*)(al + k4 * 8 + 4) = l23;
            }
        }
        {
            const int nn = fillRow;
            const uint4* sh = (const uint4*)(whi + (size_t)nn * D + kstage + fillSub);
            const uint4* sl = (const uint4*)(wlo + (size_t)nn * D + kstage + fillSub);
            uint4* bh = (uint4*)(smem + BHI_OFF + nn * LDS_STRIDE_B + fillSub * 2);
            uint4* bl = (uint4*)(smem + BLO_OFF + nn * LDS_STRIDE_B + fillSub * 2);
#pragma unroll
            for (int q = 0; q < 4; q++) { bh[q] = sh[q]; bl[q] = sl[q]; }
        }
        __syncthreads();

#pragma unroll
        for (int ks = 0; ks < 4; ks++) {
            const uint32_t kb = (uint32_t)(ks * 32);
            uint32_t ah0, ah1, ah2, ah3, al0, al1, al2, al3;
            ldmx4(ah0, ah1, ah2, ah3, sb + AHI_OFF + aOffBytes + kb);
            ldmx4(al0, al1, al2, al3, sb + ALO_OFF + aOffBytes + kb);
#pragma unroll
            for (int nc = 0; nc < 8; nc++) {
                const uint32_t bAddr = bOffBytes + (uint32_t)(nc * 16 * LDS_STRIDE_B) + kb;
                uint32_t bh0, bh1, bh2, bh3, bl0, bl1, bl2, bl3;
                ldmx4(bh0, bh1, bh2, bh3, sb + BHI_OFF + bAddr);
                ldmx4(bl0, bl1, bl2, bl3, sb + BLO_OFF + bAddr);
                float* c0 = acc[nc * 2];
                float* c1 = acc[nc * 2 + 1];
                mma_bf16(c0[0], c0[1], c0[2], c0[3], ah0, ah1, ah2, ah3, bh0, bh1);
                mma_bf16(c0[0], c0[1], c0[2], c0[3], ah0, ah1, ah2, ah3, bl0, bl1);
                mma_bf16(c0[0], c0[1], c0[2], c0[3], al0, al1, al2, al3, bh0, bh1);
                mma_bf16(c1[0], c1[1], c1[2], c1[3], ah0, ah1, ah2, ah3, bh2, bh3);
                mma_bf16(c1[0], c1[1], c1[2], c1[3], ah0, ah1, ah2, ah3, bl2, bl3);
                mma_bf16(c1[0], c1[1], c1[2], c1[3], al0, al1, al2, al3, bh2, bh3);
            }
        }
        __syncthreads();
    }

    const int rTop = rbase + m0 + (lane >> 2);
    const int cOff = (lane & 3) * 2;
#pragma unroll
    for (int t = 0; t < 16; t++) {
        const int col = t * 8 + cOff;
        float bx = 0.f, by = 0.f;
        if (BIAS) { bx = bias[col]; by = bias[col + 1]; }
        if (rTop < n) {
            float2 v = make_float2(acc[t][0] + bx, acc[t][1] + by);
            *(float2*)(out + (size_t)rTop * D + col) = v;
        }
        if (rTop + 8 < n) {
            float2 v = make_float2(acc[t][2] + bx, acc[t][3] + by);
            *(float2*)(out + (size_t)(rTop + 8) * D + col) = v;
        }
    }
}

// ---------------- zero packed counters ----------------------------------------
__global__ void k_zero(int n) {
    int i = blockIdx.x * blockDim.x + threadIdx.x;
    if (i < n) g_pack[i] = 0ull;
}

// ---------------- degree+count accumulation (detect folded in) ----------------
__global__ void k_deg_accum(const void* __restrict__ ei_raw,
                            const float* __restrict__ w, int E, int n) {
    __shared__ int s_nz;
    if (threadIdx.x == 0) s_nz = 0;
    __syncthreads();
    if (threadIdx.x < 64) {
        if (((const int*)ei_raw)[2 * threadIdx.x + 1] != 0) s_nz = 1;  // benign race
    }
    __syncthreads();
    const int is64 = (s_nz == 0);

    int e = blockIdx.x * blockDim.x + threadIdx.x;
    if (e >= E) return;
    int s, d;
    if (is64) {
        const long long* ei = (const long long*)ei_raw;
        s = (int)ei[e]; d = (int)ei[E + e];
    } else {
        const int* ei = (const int*)ei_raw;
        s = ei[e]; d = ei[E + e];
    }
    if ((unsigned)s >= (unsigned)n) s = 0;
    if ((unsigned)d >= (unsigned)n) d = 0;
    g_src[e] = s; g_dst[e] = d;
    unsigned long long inc = (1ull << 32) |
        (unsigned long long)(unsigned)__float2uint_rn(w[e] * DEG_SCALE);
    unsigned long long old = atomicAdd(&g_pack[d], inc);
    g_eidx[e] = (int)(old >> 32);
}

// ---------------- CSR build (scan1 also computes dinv) -------------------------
__global__ void k_scan1(int n) {
    __shared__ int sh[SCAN_B];
    int i = blockIdx.x * SCAN_B + threadIdx.x;
    int v = 0;
    if (i < n) {
        unsigned long long p = g_pack[i];
        v = (int)(p >> 32);
        float deg = 1.0f + (float)(unsigned)(p & 0xFFFFFFFFull) * (1.0f / DEG_SCALE);
        g_dinv[i] = rsqrtf(deg);
    }
    sh[threadIdx.x] = v;
    __syncthreads();
    for (int o = 1; o < SCAN_B; o <<= 1) {
        int t = (threadIdx.x >= o) ? sh[threadIdx.x - o] : 0;
        __syncthreads();
        sh[threadIdx.x] += t;
        __syncthreads();
    }
    if (i < n) g_rowtmp[i] = sh[threadIdx.x] - v;
    if (threadIdx.x == SCAN_B - 1) g_bsum[blockIdx.x] = sh[SCAN_B - 1];
}

__global__ void k_scan2(int nb) {
    __shared__ int sh[SCAN_B];
    int v = (threadIdx.x < nb) ? g_bsum[threadIdx.x] : 0;
    sh[threadIdx.x] = v;
    __syncthreads();
    for (int o = 1; o < SCAN_B; o <<= 1) {
        int t = (threadIdx.x >= o) ? sh[threadIdx.x - o] : 0;
        __syncthreads();
        sh[threadIdx.x] += t;
        __syncthreads();
    }
    g_boff[threadIdx.x] = sh[threadIdx.x] - v;
}

__global__ void k_scan3(int n, int E) {
    int i = blockIdx.x * blockDim.x + threadIdx.x;
    if (i < n) g_rowptr[i] = g_rowtmp[i] + g_boff[i / SCAN_B];
    if (i == 0) g_rowptr[n] = E;
}

// ---------------- fill: csr = (src, nrm) ---------------------------------------
__global__ void k_fill(const float* __restrict__ w, int E) {
    int e = blockIdx.x * blockDim.x + threadIdx.x;
    if (e >= E) return;
    int s   = g_src[e];
    int d   = g_dst[e];
    int pos = g_rowptr[d] + g_eidx[e];
    float nrm = g_dinv[s] * w[e] * g_dinv[d];
    int2 v;
    v.x = s;
    v.y = __float_as_int(nrm);
    g_csr[pos] = v;
}

// ---------------- fused aggregation (node range [n0base, nlim)) ---------------
__global__ void __launch_bounds__(256)
k_agg(const float* __restrict__ bias, int n0base, int nlim) {
    int node = n0base + ((blockIdx.x * blockDim.x + threadIdx.x) >> 5);
    int lane = threadIdx.x & 31;
    if (node >= nlim) return;

    int beg = g_rowptr[node];
    int end = g_rowptr[node + 1];
    float di = g_dinv[node];
    float s  = di * di;

    float4 hv = *(const float4*)(g_h + (size_t)node * D + lane * 4);
    float4 bv = *(const float4*)(bias + lane * 4);
    float ax = fmaf(hv.x, s, bv.x);
    float ay = fmaf(hv.y, s, bv.y);
    float az = fmaf(hv.z, s, bv.z);
    float aw = fmaf(hv.w, s, bv.w);

    int e = beg;
    for (; e + 3 < end; e += 4) {
        int2 c0 = g_csr[e];
        int2 c1 = g_csr[e + 1];
        int2 c2 = g_csr[e + 2];
        int2 c3 = g_csr[e + 3];
        float4 h0 = *(const float4*)(g_h + (size_t)c0.x * D + lane * 4);
        float4 h1 = *(const float4*)(g_h + (size_t)c1.x * D + lane * 4);
        float4 h2 = *(const float4*)(g_h + (size_t)c2.x * D + lane * 4);
        float4 h3 = *(const float4*)(g_h + (size_t)c3.x * D + lane * 4);
        float n0 = __int_as_float(c0.y), n1 = __int_as_float(c1.y);
        float n2 = __int_as_float(c2.y), n3 = __int_as_float(c3.y);
        ax = fmaf(h0.x, n0, ax); ay = fmaf(h0.y, n0, ay);
        az = fmaf(h0.z, n0, az); aw = fmaf(h0.w, n0, aw);
        ax = fmaf(h1.x, n1, ax); ay = fmaf(h1.y, n1, ay);
        az = fmaf(h1.z, n1, az); aw = fmaf(h1.w, n1, aw);
        ax = fmaf(h2.x, n2, ax); ay = fmaf(h2.y, n2, ay);
        az = fmaf(h2.z, n2, az); aw = fmaf(h2.w, n2, aw);
        ax = fmaf(h3.x, n3, ax); ay = fmaf(h3.y, n3, ay);
        az = fmaf(h3.z, n3, az); aw = fmaf(h3.w, n3, aw);
    }
    for (; e < end; e++) {
        int2 c0 = g_csr[e];
        float n0 = __int_as_float(c0.y);
        float4 h0 = *(const float4*)(g_h + (size_t)c0.x * D + lane * 4);
        ax = fmaf(h0.x, n0, ax); ay = fmaf(h0.y, n0, ay);
        az = fmaf(h0.z, n0, az); aw = fmaf(h0.w, n0, aw);
    }
    *(float4*)(g_out + (size_t)node * D + lane * 4) = make_float4(ax, ay, az, aw);
}

// ---------------- host launcher ----------------------------------------------
extern "C" void kernel_launch(void* const* d_in, const int* in_sizes, int n_in,
                              void* d_out, int out_size) {
    const float* x  = (const float*)d_in[0];
    const void*  ei = d_in[1];
    const float* ew = (const float*)d_in[2];
    const float* W1 = (const float*)d_in[3];
    const float* b1 = (const float*)d_in[4];
    const float* W2 = (const float*)d_in[5];
    const float* b2 = (const float*)d_in[6];
    const float* W3 = (const float*)d_in[7];
    const float* b3 = (const float*)d_in[8];
    const float* Wl = (const float*)d_in[9];
    const float* bl = (const float*)d_in[10];
    float* out = (float*)d_out;

    const int N = in_sizes[0] / D;
    const int E = in_sizes[2];
    const int NH = N / 2;                   // chunk split point

    float *dh = nullptr, *dout = nullptr;
    unsigned short *whi = nullptr, *wlo = nullptr;
    cudaGetSymbolAddress((void**)&dh,   g_h);
    cudaGetSymbolAddress((void**)&dout, g_out);
    cudaGetSymbolAddress((void**)&whi,  g_whi);
    cudaGetSymbolAddress((void**)&wlo,  g_wlo);

    cudaFuncSetAttribute(k_tgemm<false, false>, cudaFuncAttributeMaxDynamicSharedMemorySize, SM_TOTAL);
    cudaFuncSetAttribute(k_tgemm<true,  false>, cudaFuncAttributeMaxDynamicSharedMemorySize, SM_TOTAL);
    cudaFuncSetAttribute(k_tgemm<false, true>,  cudaFuncAttributeMaxDynamicSharedMemorySize, SM_TOTAL);

    static cudaStream_t s_side = nullptr;
    static cudaEvent_t  s_fork = nullptr, s_join = nullptr;
    static cudaEvent_t  s_eA[4] = {}, s_eG[4] = {};
    if (!s_side) {
        cudaStreamCreateWithFlags(&s_side, cudaStreamNonBlocking);
        cudaEventCreateWithFlags(&s_fork, cudaEventDisableTiming);
        cudaEventCreateWithFlags(&s_join, cudaEventDisableTiming);
        for (int i = 0; i < 4; i++) {
            cudaEventCreateWithFlags(&s_eA[i], cudaEventDisableTiming);
            cudaEventCreateWithFlags(&s_eG[i], cudaEventDisableTiming);
        }
    }

    const int T  = 256;
    const int gN = (N + T - 1) / T;
    const int gE = (E + T - 1) / T;
    const int gGF = (N + TM - 1) / TM;             // full gemm grid
    const int gG0 = (NH + TM - 1) / TM;            // chunk0 gemm grid
    const int gG1 = (N - NH + TM - 1) / TM;        // chunk1 gemm grid
    const int gA0 = (NH * 32 + T - 1) / T;         // chunk0 agg grid
    const int gA1 = ((N - NH) * 32 + T - 1) / T;   // chunk1 agg grid
    const int nb = (N + SCAN_B - 1) / SCAN_B;

    // --- fork: side does weight split + full layer-1 GEMM (no edge deps) ---
    cudaEventRecord(s_fork, 0);
    cudaStreamWaitEvent(s_side, s_fork, 0);
    k_wsplit<<<64, dim3(32, 8), 0, s_side>>>(W1, W2, W3, Wl);
    k_tgemm<false, false><<<gGF, T, SM_TOTAL, s_side>>>(x, whi, wlo, nullptr, dh, 0, N);
    cudaEventRecord(s_join, s_side);

    // --- main: edge prep chain (concurrent with side) ---
    k_zero     <<<gN, T>>>(N);
    k_deg_accum<<<gE, T>>>(ei, ew, E, N);
    k_scan1    <<<nb, SCAN_B>>>(N);
    k_scan2    <<<1,  SCAN_B>>>(nb);
    k_scan3    <<<gN, T>>>(N, E);
    k_fill     <<<gE, T>>>(ew, E);
    cudaStreamWaitEvent(0, s_join, 0);

    // pipelined boundary: agg_L(c0) -> [side: gemm_{L+1}(c0)] || agg_L(c1) -> gemm_{L+1}(c1)
    const unsigned short* Wp[3] = { whi + 16384, whi + 2 * 16384, whi + 3 * 16384 };
    const unsigned short* Lp[3] = { wlo + 16384, wlo + 2 * 16384, wlo + 3 * 16384 };
    const float* Bs[3] = { b1, b2, b3 };

    for (int L = 0; L < 3; L++) {
        // agg chunk 0 then chunk 1 on main
        k_agg<<<gA0, T>>>(Bs[L], 0, NH);
        cudaEventRecord(s_eA[L], 0);
        k_agg<<<gA1, T>>>(Bs[L], NH, N);
        // side: gemm chunk 0 as soon as agg chunk 0 done
        cudaStreamWaitEvent(s_side, s_eA[L], 0);
        if (L < 2)
            k_tgemm<true, false><<<gG0, T, SM_TOTAL, s_side>>>(dout, Wp[L], Lp[L], nullptr, dh, 0, NH);
        else
            k_tgemm<false, true><<<gG0, T, SM_TOTAL, s_side>>>(dout, Wp[L], Lp[L], bl, out, 0, NH);
        cudaEventRecord(s_eG[L], s_side);
        // main: gemm chunk 1
        if (L < 2)
            k_tgemm<true, false><<<gG1, T, SM_TOTAL>>>(dout, Wp[L], Lp[L], nullptr, dh, NH, N);
        else
            k_tgemm<false, true><<<gG1, T, SM_TOTAL>>>(dout, Wp[L], Lp[L], bl, out, NH, N);
        cudaStreamWaitEvent(0, s_eG[L], 0);
    }
}

// round 12
// speedup vs baseline: 1.0489x; 1.0489x over previous
#include <cuda_runtime.h>
#include <cuda_bf16.h>
#include <cstdint>

#define NN 50000
#define NE 800000
#define D  128
#define SCAN_B 256
#define TM 128

#define LDS_STRIDE_B 144
#define AHI_OFF 0
#define ALO_OFF 18432
#define BHI_OFF 36864
#define BLO_OFF 55296
#define SM_TOTAL 73728

#define DEG_SCALE 4194304.0f

// ---------------- scratch (static device globals; no allocation) -------------
__device__ float g_h  [NN * D];              // GEMM output (fp32, gather source)
__device__ unsigned short g_ahi[NN * D];     // agg output, bf16 hi (relu'd)
__device__ unsigned short g_alo[NN * D];     // agg output, bf16 lo
__device__ int   g_src [NE];
__device__ int   g_dst [NE];
__device__ int   g_eidx[NE];
__device__ unsigned long long g_pack[NN];
__device__ float g_dinv[NN];
// CSR (by dst)
__device__ int   g_rowtmp[NN];
__device__ int   g_rowptr[NN + 1];
__device__ int   g_bsum  [SCAN_B];
__device__ int   g_boff  [SCAN_B];
__device__ int2  g_csr   [NE];               // .x = src, .y = bitcast(norm)
// pre-split transposed weights
__device__ unsigned short g_whi[4 * 16384];
__device__ unsigned short g_wlo[4 * 16384];

// ---------------- helpers ------------------------------------------------------
__device__ __forceinline__ uint32_t smem_u32(const void* p) {
    uint32_t a;
    asm("{ .reg .u64 t; cvta.to.shared.u64 t, %1; cvt.u32.u64 %0, t; }" : "=r"(a) : "l"(p));
    return a;
}

__device__ __forceinline__ void ldmx4(uint32_t& r0, uint32_t& r1, uint32_t& r2,
                                      uint32_t& r3, uint32_t addr) {
    asm volatile("ldmatrix.sync.aligned.m8n8.x4.shared.b16 {%0,%1,%2,%3}, [%4];"
                 : "=r"(r0), "=r"(r1), "=r"(r2), "=r"(r3) : "r"(addr));
}

__device__ __forceinline__ void mma_bf16(float& c0, float& c1, float& c2, float& c3,
                                         uint32_t a0, uint32_t a1, uint32_t a2, uint32_t a3,
                                         uint32_t b0, uint32_t b1) {
    asm volatile("mma.sync.aligned.m16n8k16.row.col.f32.bf16.bf16.f32 "
                 "{%0,%1,%2,%3}, {%4,%5,%6,%7}, {%8,%9}, {%0,%1,%2,%3};"
                 : "+f"(c0), "+f"(c1), "+f"(c2), "+f"(c3)
                 : "r"(a0), "r"(a1), "r"(a2), "r"(a3), "r"(b0), "r"(b1));
}

__device__ __forceinline__ void split2(float x, float y, uint32_t& hi, uint32_t& lo) {
    __nv_bfloat16 hx = __float2bfloat16(x), hy = __float2bfloat16(y);
    __nv_bfloat16 lx = __float2bfloat16(x - __bfloat162float(hx));
    __nv_bfloat16 ly = __float2bfloat16(y - __bfloat162float(hy));
    hi = (uint32_t)__bfloat16_as_ushort(hx) | ((uint32_t)__bfloat16_as_ushort(hy) << 16);
    lo = (uint32_t)__bfloat16_as_ushort(lx) | ((uint32_t)__bfloat16_as_ushort(ly) << 16);
}

// ---------------- weight pre-split (side stream; no edge deps) ----------------
__global__ void k_wsplit(const float* __restrict__ W0, const float* __restrict__ W1,
                         const float* __restrict__ W2, const float* __restrict__ W3) {
    __shared__ float tile[32][33];
    const int b  = blockIdx.x;
    const int w  = b >> 4;
    const int k0 = ((b >> 2) & 3) * 32;
    const int n0 = (b & 3) * 32;
    const float* W = (w == 0) ? W0 : (w == 1) ? W1 : (w == 2) ? W2 : W3;
    const int tx = threadIdx.x, ty = threadIdx.y;
#pragma unroll
    for (int i = 0; i < 4; i++)
        tile[ty + 8 * i][tx] = W[(size_t)(k0 + ty + 8 * i) * D + n0 + tx];
    __syncthreads();
#pragma unroll
    for (int i = 0; i < 4; i++) {
        float v = tile[tx][ty + 8 * i];
        __nv_bfloat16 h = __float2bfloat16(v);
        __nv_bfloat16 l = __float2bfloat16(v - __bfloat162float(h));
        size_t idx = (size_t)w * 16384 + (size_t)(n0 + ty + 8 * i) * D + k0 + tx;
        g_whi[idx] = __bfloat16_as_ushort(h);
        g_wlo[idx] = __bfloat16_as_ushort(l);
    }
}

// ---------------- tensor-core GEMM --------------------------------------------
// AMODE 0: A from fp32 `in` (split in-kernel). AMODE 1: A from g_ahi/g_alo copies.
template <int AMODE, bool BIAS>
__global__ void __launch_bounds__(256)
k_tgemm(const float* __restrict__ in, const unsigned short* __restrict__ whi,
        const unsigned short* __restrict__ wlo,
        const float* __restrict__ bias, float* __restrict__ out, int n) {
    extern __shared__ char smem[];
    const uint32_t sb  = smem_u32(smem);
    const int tid   = threadIdx.x;
    const int wid   = tid >> 5;
    const int lane  = tid & 31;
    const int rbase = blockIdx.x * TM;

    const int m0 = wid * 16;
    const int rowInA = (lane & 7) + ((lane >> 3) & 1) * 8;
    const int kAddA  = (lane >> 4) * 8;
    const uint32_t aOffBytes = (uint32_t)((m0 + rowInA) * LDS_STRIDE_B + kAddA * 2);
    const int rowInB = (lane & 7) + (lane >> 4) * 8;
    const int kAddB  = ((lane >> 3) & 1) * 8;
    const uint32_t bOffBytes = (uint32_t)(rowInB * LDS_STRIDE_B + kAddB * 2);

    float acc[16][4];
#pragma unroll
    for (int t = 0; t < 16; t++) {
        acc[t][0] = 0.f; acc[t][1] = 0.f; acc[t][2] = 0.f; acc[t][3] = 0.f;
    }

    const int fillRow = tid >> 1;
    const int fillSub = (tid & 1) * 32;

#pragma unroll
    for (int stage = 0; stage < 2; stage++) {
        const int kstage = stage * 64;
        // ---- A fill ----
        {
            const int r = rbase + fillRow;
            char* ah = smem + AHI_OFF + fillRow * LDS_STRIDE_B + fillSub * 2;
            char* al = smem + ALO_OFF + fillRow * LDS_STRIDE_B + fillSub * 2;
            if (AMODE == 0) {
                const float4* src = (const float4*)(in + (size_t)r * D + kstage + fillSub);
#pragma unroll
                for (int k4 = 0; k4 < 8; k4++) {
                    float4 v = (r < n) ? src[k4] : make_float4(0.f, 0.f, 0.f, 0.f);
                    uint32_t h01, l01, h23, l23;
                    split2(v.x, v.y, h01, l01);
                    split2(v.z, v.w, h23, l23);
                    *(uint32_t*)(ah + k4 * 8)     = h01;
                    *(uint32_t*)(ah + k4 * 8 + 4) = h23;
                    *(uint32_t*)(al + k4 * 8)     = l01;
                    *(uint32_t*)(al + k4 * 8 + 4) = l23;
                }
            } else {
                const uint4* sh = (const uint4*)(g_ahi + (size_t)r * D + kstage + fillSub);
                const uint4* sl = (const uint4*)(g_alo + (size_t)r * D + kstage + fillSub);
                if (r < n) {
#pragma unroll
                    for (int q = 0; q < 4; q++) {
                        ((uint4*)ah)[q] = sh[q];
                        ((uint4*)al)[q] = sl[q];
                    }
                } else {
                    uint4 z = make_uint4(0, 0, 0, 0);
#pragma unroll
                    for (int q = 0; q < 4; q++) { ((uint4*)ah)[q] = z; ((uint4*)al)[q] = z; }
                }
            }
        }
        // ---- B fill: uint4 copies from pre-split weights ----
        {
            const int nn = fillRow;
            const uint4* sh = (const uint4*)(whi + (size_t)nn * D + kstage + fillSub);
            const uint4* sl = (const uint4*)(wlo + (size_t)nn * D + kstage + fillSub);
            uint4* bh = (uint4*)(smem + BHI_OFF + nn * LDS_STRIDE_B + fillSub * 2);
            uint4* bl = (uint4*)(smem + BLO_OFF + nn * LDS_STRIDE_B + fillSub * 2);
#pragma unroll
            for (int q = 0; q < 4; q++) { bh[q] = sh[q]; bl[q] = sl[q]; }
        }
        __syncthreads();

#pragma unroll
        for (int ks = 0; ks < 4; ks++) {
            const uint32_t kb = (uint32_t)(ks * 32);
            uint32_t ah0, ah1, ah2, ah3, al0, al1, al2, al3;
            ldmx4(ah0, ah1, ah2, ah3, sb + AHI_OFF + aOffBytes + kb);
            ldmx4(al0, al1, al2, al3, sb + ALO_OFF + aOffBytes + kb);
#pragma unroll
            for (int nc = 0; nc < 8; nc++) {
                const uint32_t bAddr = bOffBytes + (uint32_t)(nc * 16 * LDS_STRIDE_B) + kb;
                uint32_t bh0, bh1, bh2, bh3, bl0, bl1, bl2, bl3;
                ldmx4(bh0, bh1, bh2, bh3, sb + BHI_OFF + bAddr);
                ldmx4(bl0, bl1, bl2, bl3, sb + BLO_OFF + bAddr);
                float* c0 = acc[nc * 2];
                float* c1 = acc[nc * 2 + 1];
                mma_bf16(c0[0], c0[1], c0[2], c0[3], ah0, ah1, ah2, ah3, bh0, bh1);
                mma_bf16(c0[0], c0[1], c0[2], c0[3], ah0, ah1, ah2, ah3, bl0, bl1);
                mma_bf16(c0[0], c0[1], c0[2], c0[3], al0, al1, al2, al3, bh0, bh1);
                mma_bf16(c1[0], c1[1], c1[2], c1[3], ah0, ah1, ah2, ah3, bh2, bh3);
                mma_bf16(c1[0], c1[1], c1[2], c1[3], ah0, ah1, ah2, ah3, bl2, bl3);
                mma_bf16(c1[0], c1[1], c1[2], c1[3], al0, al1, al2, al3, bh2, bh3);
            }
        }
        __syncthreads();
    }

    const int rTop = rbase + m0 + (lane >> 2);
    const int cOff = (lane & 3) * 2;
#pragma unroll
    for (int t = 0; t < 16; t++) {
        const int col = t * 8 + cOff;
        float bx = 0.f, by = 0.f;
        if (BIAS) { bx = bias[col]; by = bias[col + 1]; }
        if (rTop < n) {
            float2 v = make_float2(acc[t][0] + bx, acc[t][1] + by);
            *(float2*)(out + (size_t)rTop * D + col) = v;
        }
        if (rTop + 8 < n) {
            float2 v = make_float2(acc[t][2] + bx, acc[t][3] + by);
            *(float2*)(out + (size_t)(rTop + 8) * D + col) = v;
        }
    }
}

// ---------------- zero packed counters ----------------------------------------
__global__ void k_zero(int n) {
    int i = blockIdx.x * blockDim.x + threadIdx.x;
    if (i < n) g_pack[i] = 0ull;
}

// ---------------- degree+count accumulation (detect folded in) ----------------
__global__ void k_deg_accum(const void* __restrict__ ei_raw,
                            const float* __restrict__ w, int E, int n) {
    __shared__ int s_nz;
    if (threadIdx.x == 0) s_nz = 0;
    __syncthreads();
    if (threadIdx.x < 64) {
        if (((const int*)ei_raw)[2 * threadIdx.x + 1] != 0) s_nz = 1;  // benign race
    }
    __syncthreads();
    const int is64 = (s_nz == 0);

    int e = blockIdx.x * blockDim.x + threadIdx.x;
    if (e >= E) return;
    int s, d;
    if (is64) {
        const long long* ei = (const long long*)ei_raw;
        s = (int)ei[e]; d = (int)ei[E + e];
    } else {
        const int* ei = (const int*)ei_raw;
        s = ei[e]; d = ei[E + e];
    }
    if ((unsigned)s >= (unsigned)n) s = 0;
    if ((unsigned)d >= (unsigned)n) d = 0;
    g_src[e] = s; g_dst[e] = d;
    unsigned long long inc = (1ull << 32) |
        (unsigned long long)(unsigned)__float2uint_rn(w[e] * DEG_SCALE);
    unsigned long long old = atomicAdd(&g_pack[d], inc);
    g_eidx[e] = (int)(old >> 32);
}

// ---------------- CSR build (scan1 also computes dinv) -------------------------
__global__ void k_scan1(int n) {
    __shared__ int sh[SCAN_B];
    int i = blockIdx.x * SCAN_B + threadIdx.x;
    int v = 0;
    if (i < n) {
        unsigned long long p = g_pack[i];
        v = (int)(p >> 32);
        float deg = 1.0f + (float)(unsigned)(p & 0xFFFFFFFFull) * (1.0f / DEG_SCALE);
        g_dinv[i] = rsqrtf(deg);
    }
    sh[threadIdx.x] = v;
    __syncthreads();
    for (int o = 1; o < SCAN_B; o <<= 1) {
        int t = (threadIdx.x >= o) ? sh[threadIdx.x - o] : 0;
        __syncthreads();
        sh[threadIdx.x] += t;
        __syncthreads();
    }
    if (i < n) g_rowtmp[i] = sh[threadIdx.x] - v;
    if (threadIdx.x == SCAN_B - 1) g_bsum[blockIdx.x] = sh[SCAN_B - 1];
}

__global__ void k_scan2(int nb) {
    __shared__ int sh[SCAN_B];
    int v = (threadIdx.x < nb) ? g_bsum[threadIdx.x] : 0;
    sh[threadIdx.x] = v;
    __syncthreads();
    for (int o = 1; o < SCAN_B; o <<= 1) {
        int t = (threadIdx.x >= o) ? sh[threadIdx.x - o] : 0;
        __syncthreads();
        sh[threadIdx.x] += t;
        __syncthreads();
    }
    g_boff[threadIdx.x] = sh[threadIdx.x] - v;
}

__global__ void k_scan3(int n, int E) {
    int i = blockIdx.x * blockDim.x + threadIdx.x;
    if (i < n) g_rowptr[i] = g_rowtmp[i] + g_boff[i / SCAN_B];
    if (i == 0) g_rowptr[n] = E;
}

// ---------------- fill: csr = (src, nrm) ---------------------------------------
__global__ void k_fill(const float* __restrict__ w, int E) {
    int e = blockIdx.x * blockDim.x + threadIdx.x;
    if (e >= E) return;
    int s   = g_src[e];
    int d   = g_dst[e];
    int pos = g_rowptr[d] + g_eidx[e];
    float nrm = g_dinv[s] * w[e] * g_dinv[d];
    int2 v;
    v.x = s;
    v.y = __float_as_int(nrm);
    g_csr[pos] = v;
}

// ---------------- fused aggregation + bias + (relu) + bf16 split --------------
template <bool RELU>
__global__ void __launch_bounds__(256)
k_agg(const float* __restrict__ bias, int n) {
    int node = (blockIdx.x * blockDim.x + threadIdx.x) >> 5;
    int lane = threadIdx.x & 31;
    if (node >= n) return;

    int beg = g_rowptr[node];
    int end = g_rowptr[node + 1];
    float di = g_dinv[node];
    float s  = di * di;

    float4 hv = *(const float4*)(g_h + (size_t)node * D + lane * 4);
    float4 bv = *(const float4*)(bias + lane * 4);
    float ax = fmaf(hv.x, s, bv.x);
    float ay = fmaf(hv.y, s, bv.y);
    float az = fmaf(hv.z, s, bv.z);
    float aw = fmaf(hv.w, s, bv.w);

    int e = beg;
    for (; e + 3 < end; e += 4) {
        int2 c0 = g_csr[e];
        int2 c1 = g_csr[e + 1];
        int2 c2 = g_csr[e + 2];
        int2 c3 = g_csr[e + 3];
        float4 h0 = *(const float4*)(g_h + (size_t)c0.x * D + lane * 4);
        float4 h1 = *(const float4*)(g_h + (size_t)c1.x * D + lane * 4);
        float4 h2 = *(const float4*)(g_h + (size_t)c2.x * D + lane * 4);
        float4 h3 = *(const float4*)(g_h + (size_t)c3.x * D + lane * 4);
        float n0 = __int_as_float(c0.y), n1 = __int_as_float(c1.y);
        float n2 = __int_as_float(c2.y), n3 = __int_as_float(c3.y);
        ax = fmaf(h0.x, n0, ax); ay = fmaf(h0.y, n0, ay);
        az = fmaf(h0.z, n0, az); aw = fmaf(h0.w, n0, aw);
        ax = fmaf(h1.x, n1, ax); ay = fmaf(h1.y, n1, ay);
        az = fmaf(h1.z, n1, az); aw = fmaf(h1.w, n1, aw);
        ax = fmaf(h2.x, n2, ax); ay = fmaf(h2.y, n2, ay);
        az = fmaf(h2.z, n2, az); aw = fmaf(h2.w, n2, aw);
        ax = fmaf(h3.x, n3, ax); ay = fmaf(h3.y, n3, ay);
        az = fmaf(h3.z, n3, az); aw = fmaf(h3.w, n3, aw);
    }
    for (; e < end; e++) {
        int2 c0 = g_csr[e];
        float n0 = __int_as_float(c0.y);
        float4 h0 = *(const float4*)(g_h + (size_t)c0.x * D + lane * 4);
        ax = fmaf(h0.x, n0, ax); ay = fmaf(h0.y, n0, ay);
        az = fmaf(h0.z, n0, az); aw = fmaf(h0.w, n0, aw);
    }

    if (RELU) {
        ax = fmaxf(ax, 0.f); ay = fmaxf(ay, 0.f);
        az = fmaxf(az, 0.f); aw = fmaxf(aw, 0.f);
    }
    uint32_t h01, l01, h23, l23;
    split2(ax, ay, h01, l01);
    split2(az, aw, h23, l23);
    size_t base = (size_t)node * D + lane * 4;   // ushort index, 8B aligned
    *(uint2*)(g_ahi + base) = make_uint2(h01, h23);
    *(uint2*)(g_alo + base) = make_uint2(l01, l23);
}

// ---------------- host launcher ----------------------------------------------
extern "C" void kernel_launch(void* const* d_in, const int* in_sizes, int n_in,
                              void* d_out, int out_size) {
    const float* x  = (const float*)d_in[0];
    const void*  ei = d_in[1];
    const float* ew = (const float*)d_in[2];
    const float* W1 = (const float*)d_in[3];
    const float* b1 = (const float*)d_in[4];
    const float* W2 = (const float*)d_in[5];
    const float* b2 = (const float*)d_in[6];
    const float* W3 = (const float*)d_in[7];
    const float* b3 = (const float*)d_in[8];
    const float* Wl = (const float*)d_in[9];
    const float* bl = (const float*)d_in[10];
    float* out = (float*)d_out;

    const int N = in_sizes[0] / D;
    const int E = in_sizes[2];

    float *dh = nullptr;
    unsigned short *whi = nullptr, *wlo = nullptr;
    cudaGetSymbolAddress((void**)&dh,  g_h);
    cudaGetSymbolAddress((void**)&whi, g_whi);
    cudaGetSymbolAddress((void**)&wlo, g_wlo);

    cudaFuncSetAttribute(k_tgemm<0, false>, cudaFuncAttributeMaxDynamicSharedMemorySize, SM_TOTAL);
    cudaFuncSetAttribute(k_tgemm<1, false>, cudaFuncAttributeMaxDynamicSharedMemorySize, SM_TOTAL);
    cudaFuncSetAttribute(k_tgemm<1, true>,  cudaFuncAttributeMaxDynamicSharedMemorySize, SM_TOTAL);

    static cudaStream_t s_side = nullptr;
    static cudaEvent_t  s_fork = nullptr, s_join = nullptr;
    if (!s_side) {
        cudaStreamCreateWithFlags(&s_side, cudaStreamNonBlocking);
        cudaEventCreateWithFlags(&s_fork, cudaEventDisableTiming);
        cudaEventCreateWithFlags(&s_join, cudaEventDisableTiming);
    }

    const int T  = 256;
    const int gN = (N + T - 1) / T;
    const int gE = (E + T - 1) / T;
    const int gG = (N + TM - 1) / TM;
    const int gA = (N * 32 + T - 1) / T;
    const int nb = (N + SCAN_B - 1) / SCAN_B;

    // --- fork: side does weight split + layer-1 GEMM (no edge deps) ---
    cudaEventRecord(s_fork, 0);
    cudaStreamWaitEvent(s_side, s_fork, 0);
    k_wsplit<<<64, dim3(32, 8), 0, s_side>>>(W1, W2, W3, Wl);
    k_tgemm<0, false><<<gG, T, SM_TOTAL, s_side>>>(x, whi, wlo, nullptr, dh, N);
    cudaEventRecord(s_join, s_side);

    // --- main: edge prep chain (concurrent with side) ---
    k_zero     <<<gN, T>>>(N);
    k_deg_accum<<<gE, T>>>(ei, ew, E, N);
    k_scan1    <<<nb, SCAN_B>>>(N);
    k_scan2    <<<1,  SCAN_B>>>(nb);
    k_scan3    <<<gN, T>>>(N, E);
    k_fill     <<<gE, T>>>(ew, E);
    cudaStreamWaitEvent(0, s_join, 0);

    // --- layer 1: agg (+b1, relu, split) -> gemm2 ---
    k_agg<true><<<gA, T>>>(b1, N);
    k_tgemm<1, false><<<gG, T, SM_TOTAL>>>(nullptr, whi + 16384, wlo + 16384, nullptr, dh, N);
    // --- layer 2 ---
    k_agg<true><<<gA, T>>>(b2, N);
    k_tgemm<1, false><<<gG, T, SM_TOTAL>>>(nullptr, whi + 2 * 16384, wlo + 2 * 16384, nullptr, dh, N);
    // --- layer 3 (no relu) ---
    k_agg<false><<<gA, T>>>(b3, N);
    // --- final linear ---
    k_tgemm<1, true><<<gG, T, SM_TOTAL>>>(nullptr, whi + 3 * 16384, wlo + 3 * 16384, bl, out, N);
}

// round 13
// speedup vs baseline: 1.0820x; 1.0315x over previous
#include <cuda_runtime.h>
#include <cuda_bf16.h>
#include <cstdint>

#define NN 50000
#define NE 800000
#define D  128
#define SCAN_B 256
#define TM 128

#define LDS_STRIDE_B 144
#define AHI_OFF 0
#define ALO_OFF 18432
#define BHI_OFF 36864
#define BLO_OFF 55296
#define SM_TOTAL 73728

#define DEG_SCALE 4194304.0f

// ---------------- scratch (static device globals; no allocation) -------------
__device__ float g_h  [NN * D];              // GEMM output (fp32, gather source)
__device__ unsigned short g_ahi[NN * D];     // agg output, bf16 hi (relu'd)
__device__ unsigned short g_alo[NN * D];     // agg output, bf16 lo
__device__ int   g_eidx[NE];                 // within-row slot for each edge
__device__ unsigned long long g_pack[NN];    // zero-init; scan1 restores to 0
__device__ float g_dinv[NN];
// CSR (by dst)
__device__ int   g_rowtmp[NN];
__device__ int   g_rowptr[NN + 1];
__device__ int   g_bsum  [SCAN_B];
__device__ int2  g_csr   [NE];               // .x = src, .y = bitcast(norm)
// pre-split transposed weights
__device__ unsigned short g_whi[4 * 16384];
__device__ unsigned short g_wlo[4 * 16384];

// ---------------- helpers ------------------------------------------------------
__device__ __forceinline__ uint32_t smem_u32(const void* p) {
    uint32_t a;
    asm("{ .reg .u64 t; cvta.to.shared.u64 t, %1; cvt.u32.u64 %0, t; }" : "=r"(a) : "l"(p));
    return a;
}

__device__ __forceinline__ void ldmx4(uint32_t& r0, uint32_t& r1, uint32_t& r2,
                                      uint32_t& r3, uint32_t addr) {
    asm volatile("ldmatrix.sync.aligned.m8n8.x4.shared.b16 {%0,%1,%2,%3}, [%4];"
                 : "=r"(r0), "=r"(r1), "=r"(r2), "=r"(r3) : "r"(addr));
}

__device__ __forceinline__ void mma_bf16(float& c0, float& c1, float& c2, float& c3,
                                         uint32_t a0, uint32_t a1, uint32_t a2, uint32_t a3,
                                         uint32_t b0, uint32_t b1) {
    asm volatile("mma.sync.aligned.m16n8k16.row.col.f32.bf16.bf16.f32 "
                 "{%0,%1,%2,%3}, {%4,%5,%6,%7}, {%8,%9}, {%0,%1,%2,%3};"
                 : "+f"(c0), "+f"(c1), "+f"(c2), "+f"(c3)
                 : "r"(a0), "r"(a1), "r"(a2), "r"(a3), "r"(b0), "r"(b1));
}

__device__ __forceinline__ void split2(float x, float y, uint32_t& hi, uint32_t& lo) {
    __nv_bfloat16 hx = __float2bfloat16(x), hy = __float2bfloat16(y);
    __nv_bfloat16 lx = __float2bfloat16(x - __bfloat162float(hx));
    __nv_bfloat16 ly = __float2bfloat16(y - __bfloat162float(hy));
    hi = (uint32_t)__bfloat16_as_ushort(hx) | ((uint32_t)__bfloat16_as_ushort(hy) << 16);
    lo = (uint32_t)__bfloat16_as_ushort(lx) | ((uint32_t)__bfloat16_as_ushort(ly) << 16);
}

// decode edge e (src,dst) with per-block dtype probe already done (is64 flag)
__device__ __forceinline__ void decode_edge(const void* ei_raw, int is64, int e,
                                            int E, int n, int& s, int& d) {
    if (is64) {
        const long long* ei = (const long long*)ei_raw;
        s = (int)ei[e]; d = (int)ei[E + e];
    } else {
        const int* ei = (const int*)ei_raw;
        s = ei[e]; d = ei[E + e];
    }
    if ((unsigned)s >= (unsigned)n) s = 0;
    if ((unsigned)d >= (unsigned)n) d = 0;
}

// per-block int64-vs-int32 probe (first 64 odd words)
__device__ __forceinline__ int probe_is64(const void* ei_raw) {
    __shared__ int s_nz;
    if (threadIdx.x == 0) s_nz = 0;
    __syncthreads();
    if (threadIdx.x < 64) {
        if (((const int*)ei_raw)[2 * threadIdx.x + 1] != 0) s_nz = 1;  // benign race
    }
    __syncthreads();
    return (s_nz == 0);
}

// ---------------- weight pre-split (side stream; no edge deps) ----------------
__global__ void k_wsplit(const float* __restrict__ W0, const float* __restrict__ W1,
                         const float* __restrict__ W2, const float* __restrict__ W3) {
    __shared__ float tile[32][33];
    const int b  = blockIdx.x;
    const int w  = b >> 4;
    const int k0 = ((b >> 2) & 3) * 32;
    const int n0 = (b & 3) * 32;
    const float* W = (w == 0) ? W0 : (w == 1) ? W1 : (w == 2) ? W2 : W3;
    const int tx = threadIdx.x, ty = threadIdx.y;
#pragma unroll
    for (int i = 0; i < 4; i++)
        tile[ty + 8 * i][tx] = W[(size_t)(k0 + ty + 8 * i) * D + n0 + tx];
    __syncthreads();
#pragma unroll
    for (int i = 0; i < 4; i++) {
        float v = tile[tx][ty + 8 * i];
        __nv_bfloat16 h = __float2bfloat16(v);
        __nv_bfloat16 l = __float2bfloat16(v - __bfloat162float(h));
        size_t idx = (size_t)w * 16384 + (size_t)(n0 + ty + 8 * i) * D + k0 + tx;
        g_whi[idx] = __bfloat16_as_ushort(h);
        g_wlo[idx] = __bfloat16_as_ushort(l);
    }
}

// ---------------- tensor-core GEMM --------------------------------------------
// AMODE 0: A from fp32 `in` (split in-kernel). AMODE 1: A from g_ahi/g_alo copies.
template <int AMODE, bool BIAS>
__global__ void __launch_bounds__(256)
k_tgemm(const float* __restrict__ in, const unsigned short* __restrict__ whi,
        const unsigned short* __restrict__ wlo,
        const float* __restrict__ bias, float* __restrict__ out, int n) {
    extern __shared__ char smem[];
    const uint32_t sb  = smem_u32(smem);
    const int tid   = threadIdx.x;
    const int wid   = tid >> 5;
    const int lane  = tid & 31;
    const int rbase = blockIdx.x * TM;

    const int m0 = wid * 16;
    const int rowInA = (lane & 7) + ((lane >> 3) & 1) * 8;
    const int kAddA  = (lane >> 4) * 8;
    const uint32_t aOffBytes = (uint32_t)((m0 + rowInA) * LDS_STRIDE_B + kAddA * 2);
    const int rowInB = (lane & 7) + (lane >> 4) * 8;
    const int kAddB  = ((lane >> 3) & 1) * 8;
    const uint32_t bOffBytes = (uint32_t)(rowInB * LDS_STRIDE_B + kAddB * 2);

    float acc[16][4];
#pragma unroll
    for (int t = 0; t < 16; t++) {
        acc[t][0] = 0.f; acc[t][1] = 0.f; acc[t][2] = 0.f; acc[t][3] = 0.f;
    }

    const int fillRow = tid >> 1;
    const int fillSub = (tid & 1) * 32;

#pragma unroll
    for (int stage = 0; stage < 2; stage++) {
        const int kstage = stage * 64;
        // ---- A fill ----
        {
            const int r = rbase + fillRow;
            char* ah = smem + AHI_OFF + fillRow * LDS_STRIDE_B + fillSub * 2;
            char* al = smem + ALO_OFF + fillRow * LDS_STRIDE_B + fillSub * 2;
            if (AMODE == 0) {
                const float4* src = (const float4*)(in + (size_t)r * D + kstage + fillSub);
#pragma unroll
                for (int k4 = 0; k4 < 8; k4++) {
                    float4 v = (r < n) ? src[k4] : make_float4(0.f, 0.f, 0.f, 0.f);
                    uint32_t h01, l01, h23, l23;
                    split2(v.x, v.y, h01, l01);
                    split2(v.z, v.w, h23, l23);
                    *(uint32_t*)(ah + k4 * 8)     = h01;
                    *(uint32_t*)(ah + k4 * 8 + 4) = h23;
                    *(uint32_t*)(al + k4 * 8)     = l01;
                    *(uint32_t*)(al + k4 * 8 + 4) = l23;
                }
            } else {
                const uint4* sh = (const uint4*)(g_ahi + (size_t)r * D + kstage + fillSub);
                const uint4* sl = (const uint4*)(g_alo + (size_t)r * D + kstage + fillSub);
                if (r < n) {
#pragma unroll
                    for (int q = 0; q < 4; q++) {
                        ((uint4*)ah)[q] = sh[q];
                        ((uint4*)al)[q] = sl[q];
                    }
                } else {
                    uint4 z = make_uint4(0, 0, 0, 0);
#pragma unroll
                    for (int q = 0; q < 4; q++) { ((uint4*)ah)[q] = z; ((uint4*)al)[q] = z; }
                }
            }
        }
        // ---- B fill: uint4 copies from pre-split weights ----
        {
            const int nn = fillRow;
            const uint4* sh = (const uint4*)(whi + (size_t)nn * D + kstage + fillSub);
            const uint4* sl = (const uint4*)(wlo + (size_t)nn * D + kstage + fillSub);
            uint4* bh = (uint4*)(smem + BHI_OFF + nn * LDS_STRIDE_B + fillSub * 2);
            uint4* bl = (uint4*)(smem + BLO_OFF + nn * LDS_STRIDE_B + fillSub * 2);
#pragma unroll
            for (int q = 0; q < 4; q++) { bh[q] = sh[q]; bl[q] = sl[q]; }
        }
        __syncthreads();

#pragma unroll
        for (int ks = 0; ks < 4; ks++) {
            const uint32_t kb = (uint32_t)(ks * 32);
            uint32_t ah0, ah1, ah2, ah3, al0, al1, al2, al3;
            ldmx4(ah0, ah1, ah2, ah3, sb + AHI_OFF + aOffBytes + kb);
            ldmx4(al0, al1, al2, al3, sb + ALO_OFF + aOffBytes + kb);
#pragma unroll
            for (int nc = 0; nc < 8; nc++) {
                const uint32_t bAddr = bOffBytes + (uint32_t)(nc * 16 * LDS_STRIDE_B) + kb;
                uint32_t bh0, bh1, bh2, bh3, bl0, bl1, bl2, bl3;
                ldmx4(bh0, bh1, bh2, bh3, sb + BHI_OFF + bAddr);
                ldmx4(bl0, bl1, bl2, bl3, sb + BLO_OFF + bAddr);
                float* c0 = acc[nc * 2];
                float* c1 = acc[nc * 2 + 1];
                mma_bf16(c0[0], c0[1], c0[2], c0[3], ah0, ah1, ah2, ah3, bh0, bh1);
                mma_bf16(c0[0], c0[1], c0[2], c0[3], ah0, ah1, ah2, ah3, bl0, bl1);
                mma_bf16(c0[0], c0[1], c0[2], c0[3], al0, al1, al2, al3, bh0, bh1);
                mma_bf16(c1[0], c1[1], c1[2], c1[3], ah0, ah1, ah2, ah3, bh2, bh3);
                mma_bf16(c1[0], c1[1], c1[2], c1[3], ah0, ah1, ah2, ah3, bl2, bl3);
                mma_bf16(c1[0], c1[1], c1[2], c1[3], al0, al1, al2, al3, bh2, bh3);
            }
        }
        __syncthreads();
    }

    const int rTop = rbase + m0 + (lane >> 2);
    const int cOff = (lane & 3) * 2;
#pragma unroll
    for (int t = 0; t < 16; t++) {
        const int col = t * 8 + cOff;
        float bx = 0.f, by = 0.f;
        if (BIAS) { bx = bias[col]; by = bias[col + 1]; }
        if (rTop < n) {
            float2 v = make_float2(acc[t][0] + bx, acc[t][1] + by);
            *(float2*)(out + (size_t)rTop * D + col) = v;
        }
        if (rTop + 8 < n) {
            float2 v = make_float2(acc[t][2] + bx, acc[t][3] + by);
            *(float2*)(out + (size_t)(rTop + 8) * D + col) = v;
        }
    }
}

// ---------------- degree+count accumulation ------------------------------------
// g_pack is zero on entry (static init on first run; k_scan1 re-zeroes after).
__global__ void k_deg_accum(const void* __restrict__ ei_raw,
                            const float* __restrict__ w, int E, int n) {
    const int is64 = probe_is64(ei_raw);
    int e = blockIdx.x * blockDim.x + threadIdx.x;
    if (e >= E) return;
    int s, d;
    decode_edge(ei_raw, is64, e, E, n, s, d);
    unsigned long long inc = (1ull << 32) |
        (unsigned long long)(unsigned)__float2uint_rn(w[e] * DEG_SCALE);
    unsigned long long old = atomicAdd(&g_pack[d], inc);
    g_eidx[e] = (int)(old >> 32);
}

// ---------------- CSR scan pass 1 (also dinv + g_pack reset) -------------------
__global__ void k_scan1(int n) {
    __shared__ int sh[SCAN_B];
    int i = blockIdx.x * SCAN_B + threadIdx.x;
    int v = 0;
    if (i < n) {
        unsigned long long p = g_pack[i];
        g_pack[i] = 0ull;                       // restore for next graph replay
        v = (int)(p >> 32);
        float deg = 1.0f + (float)(unsigned)(p & 0xFFFFFFFFull) * (1.0f / DEG_SCALE);
        g_dinv[i] = rsqrtf(deg);
    }
    sh[threadIdx.x] = v;
    __syncthreads();
    for (int o = 1; o < SCAN_B; o <<= 1) {
        int t = (threadIdx.x >= o) ? sh[threadIdx.x - o] : 0;
        __syncthreads();
        sh[threadIdx.x] += t;
        __syncthreads();
    }
    if (i < n) g_rowtmp[i] = sh[threadIdx.x] - v;
    if (threadIdx.x == SCAN_B - 1) g_bsum[blockIdx.x] = sh[SCAN_B - 1];
}

// ---------------- CSR scan pass 2: per-block reduce of prior block sums --------
__global__ void k_scan3(int n, int E, int nb) {
    __shared__ int red[SCAN_B];
    const int b = blockIdx.x;
    // sum of g_bsum[0 .. b-1]
    int part = (threadIdx.x < b && threadIdx.x < nb) ? g_bsum[threadIdx.x] : 0;
    red[threadIdx.x] = part;
    __syncthreads();
    for (int o = SCAN_B / 2; o > 0; o >>= 1) {
        if (threadIdx.x < o) red[threadIdx.x] += red[threadIdx.x + o];
        __syncthreads();
    }
    int boff = red[0];
    int i = b * SCAN_B + threadIdx.x;
    if (i < n) g_rowptr[i] = g_rowtmp[i] + boff;
    if (i == 0) g_rowptr[n] = E;
}

// ---------------- fill: csr = (src, nrm); re-decodes edge_index ----------------
__global__ void k_fill(const void* __restrict__ ei_raw,
                       const float* __restrict__ w, int E, int n) {
    const int is64 = probe_is64(ei_raw);
    int e = blockIdx.x * blockDim.x + threadIdx.x;
    if (e >= E) return;
    int s, d;
    decode_edge(ei_raw, is64, e, E, n, s, d);
    int pos = g_rowptr[d] + g_eidx[e];
    float nrm = g_dinv[s] * w[e] * g_dinv[d];
    int2 v;
    v.x = s;
    v.y = __float_as_int(nrm);
    g_csr[pos] = v;
}

// ---------------- fused aggregation + bias + (relu) + bf16 split --------------
template <bool RELU>
__global__ void __launch_bounds__(256)
k_agg(const float* __restrict__ bias, int n) {
    int node = (blockIdx.x * blockDim.x + threadIdx.x) >> 5;
    int lane = threadIdx.x & 31;
    if (node >= n) return;

    int beg = g_rowptr[node];
    int end = g_rowptr[node + 1];
    float di = g_dinv[node];
    float s  = di * di;

    float4 hv = *(const float4*)(g_h + (size_t)node * D + lane * 4);
    float4 bv = *(const float4*)(bias + lane * 4);
    float ax = fmaf(hv.x, s, bv.x);
    float ay = fmaf(hv.y, s, bv.y);
    float az = fmaf(hv.z, s, bv.z);
    float aw = fmaf(hv.w, s, bv.w);

    int e = beg;
    for (; e + 3 < end; e += 4) {
        int2 c0 = g_csr[e];
        int2 c1 = g_csr[e + 1];
        int2 c2 = g_csr[e + 2];
        int2 c3 = g_csr[e + 3];
        float4 h0 = *(const float4*)(g_h + (size_t)c0.x * D + lane * 4);
        float4 h1 = *(const float4*)(g_h + (size_t)c1.x * D + lane * 4);
        float4 h2 = *(const float4*)(g_h + (size_t)c2.x * D + lane * 4);
        float4 h3 = *(const float4*)(g_h + (size_t)c3.x * D + lane * 4);
        float n0 = __int_as_float(c0.y), n1 = __int_as_float(c1.y);
        float n2 = __int_as_float(c2.y), n3 = __int_as_float(c3.y);
        ax = fmaf(h0.x, n0, ax); ay = fmaf(h0.y, n0, ay);
        az = fmaf(h0.z, n0, az); aw = fmaf(h0.w, n0, aw);
        ax = fmaf(h1.x, n1, ax); ay = fmaf(h1.y, n1, ay);
        az = fmaf(h1.z, n1, az); aw = fmaf(h1.w, n1, aw);
        ax = fmaf(h2.x, n2, ax); ay = fmaf(h2.y, n2, ay);
        az = fmaf(h2.z, n2, az); aw = fmaf(h2.w, n2, aw);
        ax = fmaf(h3.x, n3, ax); ay = fmaf(h3.y, n3, ay);
        az = fmaf(h3.z, n3, az); aw = fmaf(h3.w, n3, aw);
    }
    for (; e < end; e++) {
        int2 c0 = g_csr[e];
        float n0 = __int_as_float(c0.y);
        float4 h0 = *(const float4*)(g_h + (size_t)c0.x * D + lane * 4);
        ax = fmaf(h0.x, n0, ax); ay = fmaf(h0.y, n0, ay);
        az = fmaf(h0.z, n0, az); aw = fmaf(h0.w, n0, aw);
    }

    if (RELU) {
        ax = fmaxf(ax, 0.f); ay = fmaxf(ay, 0.f);
        az = fmaxf(az, 0.f); aw = fmaxf(aw, 0.f);
    }
    uint32_t h01, l01, h23, l23;
    split2(ax, ay, h01, l01);
    split2(az, aw, h23, l23);
    size_t base = (size_t)node * D + lane * 4;
    *(uint2*)(g_ahi + base) = make_uint2(h01, h23);
    *(uint2*)(g_alo + base) = make_uint2(l01, l23);
}

// ---------------- host launcher ----------------------------------------------
extern "C" void kernel_launch(void* const* d_in, const int* in_sizes, int n_in,
                              void* d_out, int out_size) {
    const float* x  = (const float*)d_in[0];
    const void*  ei = d_in[1];
    const float* ew = (const float*)d_in[2];
    const float* W1 = (const float*)d_in[3];
    const float* b1 = (const float*)d_in[4];
    const float* W2 = (const float*)d_in[5];
    const float* b2 = (const float*)d_in[6];
    const float* W3 = (const float*)d_in[7];
    const float* b3 = (const float*)d_in[8];
    const float* Wl = (const float*)d_in[9];
    const float* bl = (const float*)d_in[10];
    float* out = (float*)d_out;

    const int N = in_sizes[0] / D;
    const int E = in_sizes[2];

    float *dh = nullptr;
    unsigned short *whi = nullptr, *wlo = nullptr;
    cudaGetSymbolAddress((void**)&dh,  g_h);
    cudaGetSymbolAddress((void**)&whi, g_whi);
    cudaGetSymbolAddress((void**)&wlo, g_wlo);

    cudaFuncSetAttribute(k_tgemm<0, false>, cudaFuncAttributeMaxDynamicSharedMemorySize, SM_TOTAL);
    cudaFuncSetAttribute(k_tgemm<1, false>, cudaFuncAttributeMaxDynamicSharedMemorySize, SM_TOTAL);
    cudaFuncSetAttribute(k_tgemm<1, true>,  cudaFuncAttributeMaxDynamicSharedMemorySize, SM_TOTAL);

    static cudaStream_t s_side = nullptr;
    static cudaEvent_t  s_fork = nullptr, s_join = nullptr;
    if (!s_side) {
        cudaStreamCreateWithFlags(&s_side, cudaStreamNonBlocking);
        cudaEventCreateWithFlags(&s_fork, cudaEventDisableTiming);
        cudaEventCreateWithFlags(&s_join, cudaEventDisableTiming);
    }

    const int T  = 256;
    const int gE = (E + T - 1) / T;
    const int gG = (N + TM - 1) / TM;
    const int gA = (N * 32 + T - 1) / T;
    const int nb = (N + SCAN_B - 1) / SCAN_B;

    // --- fork: side does weight split + layer-1 GEMM (no edge deps) ---
    cudaEventRecord(s_fork, 0);
    cudaStreamWaitEvent(s_side, s_fork, 0);
    k_wsplit<<<64, dim3(32, 8), 0, s_side>>>(W1, W2, W3, Wl);
    k_tgemm<0, false><<<gG, T, SM_TOTAL, s_side>>>(x, whi, wlo, nullptr, dh, N);
    cudaEventRecord(s_join, s_side);

    // --- main: edge prep chain (concurrent with side) ---
    k_deg_accum<<<gE, T>>>(ei, ew, E, N);
    k_scan1    <<<nb, SCAN_B>>>(N);
    k_scan3    <<<nb, SCAN_B>>>(N, E, nb);
    k_fill     <<<gE, T>>>(ei, ew, E, N);
    cudaStreamWaitEvent(0, s_join, 0);

    // --- layer 1: agg (+b1, relu, split) -> gemm2 ---
    k_agg<true><<<gA, T>>>(b1, N);
    k_tgemm<1, false><<<gG, T, SM_TOTAL>>>(nullptr, whi + 16384, wlo + 16384, nullptr, dh, N);
    // --- layer 2 ---
    k_agg<true><<<gA, T>>>(b2, N);
    k_tgemm<1, false><<<gG, T, SM_TOTAL>>>(nullptr, whi + 2 * 16384, wlo + 2 * 16384, nullptr, dh, N);
    // --- layer 3 (no relu) ---
    k_agg<false><<<gA, T>>>(b3, N);
    // --- final linear ---
    k_tgemm<1, true><<<gG, T, SM_TOTAL>>>(nullptr, whi + 3 * 16384, wlo + 3 * 16384, bl, out, N);
}

// round 14
// speedup vs baseline: 1.1419x; 1.0553x over previous
#include <cuda_runtime.h>
#include <cuda_bf16.h>
#include <cuda_fp16.h>
#include <cstdint>

#define NN 50000
#define NE 800000
#define D  128
#define SCAN_B 256
#define TM 128

#define LDS_STRIDE_B 144
#define AHI_OFF 0
#define ALO_OFF 18432
#define BHI_OFF 36864
#define BLO_OFF 55296
#define SM_TOTAL 73728

#define DEG_SCALE 4194304.0f

// ---------------- scratch (static device globals; no allocation) -------------
__device__ __half g_hf [NN * D];             // GEMM output (fp16 messages)
__device__ unsigned short g_ahi[NN * D];     // agg output, bf16 hi (relu'd)
__device__ unsigned short g_alo[NN * D];     // agg output, bf16 lo
__device__ int   g_eidx[NE];                 // within-row slot for each edge
__device__ unsigned long long g_pack[NN];    // zero-init; scan1 restores to 0
__device__ float g_dinv[NN];
// CSR (by dst)
__device__ int   g_rowtmp[NN];
__device__ int   g_rowptr[NN + 1];
__device__ int   g_bsum  [SCAN_B];
__device__ int2  g_csr   [NE];               // .x = src, .y = bitcast(norm)
// pre-split transposed weights
__device__ unsigned short g_whi[4 * 16384];
__device__ unsigned short g_wlo[4 * 16384];

// ---------------- helpers ------------------------------------------------------
__device__ __forceinline__ uint32_t smem_u32(const void* p) {
    uint32_t a;
    asm("{ .reg .u64 t; cvta.to.shared.u64 t, %1; cvt.u32.u64 %0, t; }" : "=r"(a) : "l"(p));
    return a;
}

__device__ __forceinline__ void ldmx4(uint32_t& r0, uint32_t& r1, uint32_t& r2,
                                      uint32_t& r3, uint32_t addr) {
    asm volatile("ldmatrix.sync.aligned.m8n8.x4.shared.b16 {%0,%1,%2,%3}, [%4];"
                 : "=r"(r0), "=r"(r1), "=r"(r2), "=r"(r3) : "r"(addr));
}

__device__ __forceinline__ void mma_bf16(float& c0, float& c1, float& c2, float& c3,
                                         uint32_t a0, uint32_t a1, uint32_t a2, uint32_t a3,
                                         uint32_t b0, uint32_t b1) {
    asm volatile("mma.sync.aligned.m16n8k16.row.col.f32.bf16.bf16.f32 "
                 "{%0,%1,%2,%3}, {%4,%5,%6,%7}, {%8,%9}, {%0,%1,%2,%3};"
                 : "+f"(c0), "+f"(c1), "+f"(c2), "+f"(c3)
                 : "r"(a0), "r"(a1), "r"(a2), "r"(a3), "r"(b0), "r"(b1));
}

__device__ __forceinline__ void split2(float x, float y, uint32_t& hi, uint32_t& lo) {
    __nv_bfloat16 hx = __float2bfloat16(x), hy = __float2bfloat16(y);
    __nv_bfloat16 lx = __float2bfloat16(x - __bfloat162float(hx));
    __nv_bfloat16 ly = __float2bfloat16(y - __bfloat162float(hy));
    hi = (uint32_t)__bfloat16_as_ushort(hx) | ((uint32_t)__bfloat16_as_ushort(hy) << 16);
    lo = (uint32_t)__bfloat16_as_ushort(lx) | ((uint32_t)__bfloat16_as_ushort(ly) << 16);
}

// load 4 consecutive fp16 and widen to 4 floats
__device__ __forceinline__ void ldhf4(const __half* p, float& a, float& b,
                                      float& c, float& d) {
    uint2 r = *(const uint2*)p;
    __half2 h0 = *reinterpret_cast<__half2*>(&r.x);
    __half2 h1 = *reinterpret_cast<__half2*>(&r.y);
    float2 f0 = __half22float2(h0);
    float2 f1 = __half22float2(h1);
    a = f0.x; b = f0.y; c = f1.x; d = f1.y;
}

// decode edge e (src,dst); is64 flag from per-block probe
__device__ __forceinline__ void decode_edge(const void* ei_raw, int is64, int e,
                                            int E, int n, int& s, int& d) {
    if (is64) {
        const long long* ei = (const long long*)ei_raw;
        s = (int)ei[e]; d = (int)ei[E + e];
    } else {
        const int* ei = (const int*)ei_raw;
        s = ei[e]; d = ei[E + e];
    }
    if ((unsigned)s >= (unsigned)n) s = 0;
    if ((unsigned)d >= (unsigned)n) d = 0;
}

__device__ __forceinline__ int probe_is64(const void* ei_raw) {
    __shared__ int s_nz;
    if (threadIdx.x == 0) s_nz = 0;
    __syncthreads();
    if (threadIdx.x < 64) {
        if (((const int*)ei_raw)[2 * threadIdx.x + 1] != 0) s_nz = 1;  // benign race
    }
    __syncthreads();
    return (s_nz == 0);
}

// ---------------- weight pre-split (side stream; no edge deps) ----------------
__global__ void k_wsplit(const float* __restrict__ W0, const float* __restrict__ W1,
                         const float* __restrict__ W2, const float* __restrict__ W3) {
    __shared__ float tile[32][33];
    const int b  = blockIdx.x;
    const int w  = b >> 4;
    const int k0 = ((b >> 2) & 3) * 32;
    const int n0 = (b & 3) * 32;
    const float* W = (w == 0) ? W0 : (w == 1) ? W1 : (w == 2) ? W2 : W3;
    const int tx = threadIdx.x, ty = threadIdx.y;
#pragma unroll
    for (int i = 0; i < 4; i++)
        tile[ty + 8 * i][tx] = W[(size_t)(k0 + ty + 8 * i) * D + n0 + tx];
    __syncthreads();
#pragma unroll
    for (int i = 0; i < 4; i++) {
        float v = tile[tx][ty + 8 * i];
        __nv_bfloat16 h = __float2bfloat16(v);
        __nv_bfloat16 l = __float2bfloat16(v - __bfloat162float(h));
        size_t idx = (size_t)w * 16384 + (size_t)(n0 + ty + 8 * i) * D + k0 + tx;
        g_whi[idx] = __bfloat16_as_ushort(h);
        g_wlo[idx] = __bfloat16_as_ushort(l);
    }
}

// ---------------- tensor-core GEMM --------------------------------------------
// AMODE 0: A from fp32 `in` (split in-kernel). AMODE 1: A from g_ahi/g_alo.
// OMODE 0: write fp16 to g_hf (no bias). OMODE 1: write fp32 to out (+bias).
template <int AMODE, int OMODE>
__global__ void __launch_bounds__(256)
k_tgemm(const float* __restrict__ in, const unsigned short* __restrict__ whi,
        const unsigned short* __restrict__ wlo,
        const float* __restrict__ bias, float* __restrict__ out, int n) {
    extern __shared__ char smem[];
    const uint32_t sb  = smem_u32(smem);
    const int tid   = threadIdx.x;
    const int wid   = tid >> 5;
    const int lane  = tid & 31;
    const int rbase = blockIdx.x * TM;

    const int m0 = wid * 16;
    const int rowInA = (lane & 7) + ((lane >> 3) & 1) * 8;
    const int kAddA  = (lane >> 4) * 8;
    const uint32_t aOffBytes = (uint32_t)((m0 + rowInA) * LDS_STRIDE_B + kAddA * 2);
    const int rowInB = (lane & 7) + (lane >> 4) * 8;
    const int kAddB  = ((lane >> 3) & 1) * 8;
    const uint32_t bOffBytes = (uint32_t)(rowInB * LDS_STRIDE_B + kAddB * 2);

    float acc[16][4];
#pragma unroll
    for (int t = 0; t < 16; t++) {
        acc[t][0] = 0.f; acc[t][1] = 0.f; acc[t][2] = 0.f; acc[t][3] = 0.f;
    }

    const int fillRow = tid >> 1;
    const int fillSub = (tid & 1) * 32;

#pragma unroll
    for (int stage = 0; stage < 2; stage++) {
        const int kstage = stage * 64;
        // ---- A fill ----
        {
            const int r = rbase + fillRow;
            char* ah = smem + AHI_OFF + fillRow * LDS_STRIDE_B + fillSub * 2;
            char* al = smem + ALO_OFF + fillRow * LDS_STRIDE_B + fillSub * 2;
            if (AMODE == 0) {
                const float4* src = (const float4*)(in + (size_t)r * D + kstage + fillSub);
#pragma unroll
                for (int k4 = 0; k4 < 8; k4++) {
                    float4 v = (r < n) ? src[k4] : make_float4(0.f, 0.f, 0.f, 0.f);
                    uint32_t h01, l01, h23, l23;
                    split2(v.x, v.y, h01, l01);
                    split2(v.z, v.w, h23, l23);
                    *(uint32_t*)(ah + k4 * 8)     = h01;
                    *(uint32_t*)(ah + k4 * 8 + 4) = h23;
                    *(uint32_t*)(al + k4 * 8)     = l01;
                    *(uint32_t*)(al + k4 * 8 + 4) = l23;
                }
            } else {
                const uint4* sh = (const uint4*)(g_ahi + (size_t)r * D + kstage + fillSub);
                const uint4* sl = (const uint4*)(g_alo + (size_t)r * D + kstage + fillSub);
                if (r < n) {
#pragma unroll
                    for (int q = 0; q < 4; q++) {
                        ((uint4*)ah)[q] = sh[q];
                        ((uint4*)al)[q] = sl[q];
                    }
                } else {
                    uint4 z = make_uint4(0, 0, 0, 0);
#pragma unroll
                    for (int q = 0; q < 4; q++) { ((uint4*)ah)[q] = z; ((uint4*)al)[q] = z; }
                }
            }
        }
        // ---- B fill: uint4 copies from pre-split weights ----
        {
            const int nn = fillRow;
            const uint4* sh = (const uint4*)(whi + (size_t)nn * D + kstage + fillSub);
            const uint4* sl = (const uint4*)(wlo + (size_t)nn * D + kstage + fillSub);
            uint4* bh = (uint4*)(smem + BHI_OFF + nn * LDS_STRIDE_B + fillSub * 2);
            uint4* bl = (uint4*)(smem + BLO_OFF + nn * LDS_STRIDE_B + fillSub * 2);
#pragma unroll
            for (int q = 0; q < 4; q++) { bh[q] = sh[q]; bl[q] = sl[q]; }
        }
        __syncthreads();

#pragma unroll
        for (int ks = 0; ks < 4; ks++) {
            const uint32_t kb = (uint32_t)(ks * 32);
            uint32_t ah0, ah1, ah2, ah3, al0, al1, al2, al3;
            ldmx4(ah0, ah1, ah2, ah3, sb + AHI_OFF + aOffBytes + kb);
            ldmx4(al0, al1, al2, al3, sb + ALO_OFF + aOffBytes + kb);
#pragma unroll
            for (int nc = 0; nc < 8; nc++) {
                const uint32_t bAddr = bOffBytes + (uint32_t)(nc * 16 * LDS_STRIDE_B) + kb;
                uint32_t bh0, bh1, bh2, bh3, bl0, bl1, bl2, bl3;
                ldmx4(bh0, bh1, bh2, bh3, sb + BHI_OFF + bAddr);
                ldmx4(bl0, bl1, bl2, bl3, sb + BLO_OFF + bAddr);
                float* c0 = acc[nc * 2];
                float* c1 = acc[nc * 2 + 1];
                mma_bf16(c0[0], c0[1], c0[2], c0[3], ah0, ah1, ah2, ah3, bh0, bh1);
                mma_bf16(c0[0], c0[1], c0[2], c0[3], ah0, ah1, ah2, ah3, bl0, bl1);
                mma_bf16(c0[0], c0[1], c0[2], c0[3], al0, al1, al2, al3, bh0, bh1);
                mma_bf16(c1[0], c1[1], c1[2], c1[3], ah0, ah1, ah2, ah3, bh2, bh3);
                mma_bf16(c1[0], c1[1], c1[2], c1[3], ah0, ah1, ah2, ah3, bl2, bl3);
                mma_bf16(c1[0], c1[1], c1[2], c1[3], al0, al1, al2, al3, bh2, bh3);
            }
        }
        __syncthreads();
    }

    const int rTop = rbase + m0 + (lane >> 2);
    const int cOff = (lane & 3) * 2;
#pragma unroll
    for (int t = 0; t < 16; t++) {
        const int col = t * 8 + cOff;
        if (OMODE == 0) {
            if (rTop < n) {
                __half2 v = __floats2half2_rn(acc[t][0], acc[t][1]);
                *(__half2*)(g_hf + (size_t)rTop * D + col) = v;
            }
            if (rTop + 8 < n) {
                __half2 v = __floats2half2_rn(acc[t][2], acc[t][3]);
                *(__half2*)(g_hf + (size_t)(rTop + 8) * D + col) = v;
            }
        } else {
            float bx = bias[col], by = bias[col + 1];
            if (rTop < n) {
                float2 v = make_float2(acc[t][0] + bx, acc[t][1] + by);
                *(float2*)(out + (size_t)rTop * D + col) = v;
            }
            if (rTop + 8 < n) {
                float2 v = make_float2(acc[t][2] + bx, acc[t][3] + by);
                *(float2*)(out + (size_t)(rTop + 8) * D + col) = v;
            }
        }
    }
}

// ---------------- degree+count accumulation ------------------------------------
__global__ void k_deg_accum(const void* __restrict__ ei_raw,
                            const float* __restrict__ w, int E, int n) {
    const int is64 = probe_is64(ei_raw);
    int e = blockIdx.x * blockDim.x + threadIdx.x;
    if (e >= E) return;
    int s, d;
    decode_edge(ei_raw, is64, e, E, n, s, d);
    unsigned long long inc = (1ull << 32) |
        (unsigned long long)(unsigned)__float2uint_rn(w[e] * DEG_SCALE);
    unsigned long long old = atomicAdd(&g_pack[d], inc);
    g_eidx[e] = (int)(old >> 32);
}

// ---------------- CSR scan pass 1 (also dinv + g_pack reset) -------------------
__global__ void k_scan1(int n) {
    __shared__ int sh[SCAN_B];
    int i = blockIdx.x * SCAN_B + threadIdx.x;
    int v = 0;
    if (i < n) {
        unsigned long long p = g_pack[i];
        g_pack[i] = 0ull;                       // restore for next graph replay
        v = (int)(p >> 32);
        float deg = 1.0f + (float)(unsigned)(p & 0xFFFFFFFFull) * (1.0f / DEG_SCALE);
        g_dinv[i] = rsqrtf(deg);
    }
    sh[threadIdx.x] = v;
    __syncthreads();
    for (int o = 1; o < SCAN_B; o <<= 1) {
        int t = (threadIdx.x >= o) ? sh[threadIdx.x - o] : 0;
        __syncthreads();
        sh[threadIdx.x] += t;
        __syncthreads();
    }
    if (i < n) g_rowtmp[i] = sh[threadIdx.x] - v;
    if (threadIdx.x == SCAN_B - 1) g_bsum[blockIdx.x] = sh[SCAN_B - 1];
}

// ---------------- CSR scan pass 2: per-block reduce of prior block sums --------
__global__ void k_scan3(int n, int E, int nb) {
    __shared__ int red[SCAN_B];
    const int b = blockIdx.x;
    int part = (threadIdx.x < b && threadIdx.x < nb) ? g_bsum[threadIdx.x] : 0;
    red[threadIdx.x] = part;
    __syncthreads();
    for (int o = SCAN_B / 2; o > 0; o >>= 1) {
        if (threadIdx.x < o) red[threadIdx.x] += red[threadIdx.x + o];
        __syncthreads();
    }
    int boff = red[0];
    int i = b * SCAN_B + threadIdx.x;
    if (i < n) g_rowptr[i] = g_rowtmp[i] + boff;
    if (i == 0) g_rowptr[n] = E;
}

// ---------------- fill: csr = (src, nrm); re-decodes edge_index ----------------
__global__ void k_fill(const void* __restrict__ ei_raw,
                       const float* __restrict__ w, int E, int n) {
    const int is64 = probe_is64(ei_raw);
    int e = blockIdx.x * blockDim.x + threadIdx.x;
    if (e >= E) return;
    int s, d;
    decode_edge(ei_raw, is64, e, E, n, s, d);
    int pos = g_rowptr[d] + g_eidx[e];
    float nrm = g_dinv[s] * w[e] * g_dinv[d];
    int2 v;
    v.x = s;
    v.y = __float_as_int(nrm);
    g_csr[pos] = v;
}

// ---------------- fused aggregation + bias + (relu) + bf16 split --------------
template <bool RELU>
__global__ void __launch_bounds__(256)
k_agg(const float* __restrict__ bias, int n) {
    int node = (blockIdx.x * blockDim.x + threadIdx.x) >> 5;
    int lane = threadIdx.x & 31;
    if (node >= n) return;

    int beg = g_rowptr[node];
    int end = g_rowptr[node + 1];
    float di = g_dinv[node];
    float s  = di * di;

    float hx, hy, hz, hw;
    ldhf4(g_hf + (size_t)node * D + lane * 4, hx, hy, hz, hw);
    float4 bv = *(const float4*)(bias + lane * 4);
    float ax = fmaf(hx, s, bv.x);
    float ay = fmaf(hy, s, bv.y);
    float az = fmaf(hz, s, bv.z);
    float aw = fmaf(hw, s, bv.w);

    int e = beg;
    for (; e + 3 < end; e += 4) {
        int2 c0 = g_csr[e];
        int2 c1 = g_csr[e + 1];
        int2 c2 = g_csr[e + 2];
        int2 c3 = g_csr[e + 3];
        float x0, y0, z0, w0, x1, y1, z1, w1;
        float x2, y2, z2, w2, x3, y3, z3, w3;
        ldhf4(g_hf + (size_t)c0.x * D + lane * 4, x0, y0, z0, w0);
        ldhf4(g_hf + (size_t)c1.x * D + lane * 4, x1, y1, z1, w1);
        ldhf4(g_hf + (size_t)c2.x * D + lane * 4, x2, y2, z2, w2);
        ldhf4(g_hf + (size_t)c3.x * D + lane * 4, x3, y3, z3, w3);
        float n0 = __int_as_float(c0.y), n1 = __int_as_float(c1.y);
        float n2 = __int_as_float(c2.y), n3 = __int_as_float(c3.y);
        ax = fmaf(x0, n0, ax); ay = fmaf(y0, n0, ay);
        az = fmaf(z0, n0, az); aw = fmaf(w0, n0, aw);
        ax = fmaf(x1, n1, ax); ay = fmaf(y1, n1, ay);
        az = fmaf(z1, n1, az); aw = fmaf(w1, n1, aw);
        ax = fmaf(x2, n2, ax); ay = fmaf(y2, n2, ay);
        az = fmaf(z2, n2, az); aw = fmaf(w2, n2, aw);
        ax = fmaf(x3, n3, ax); ay = fmaf(y3, n3, ay);
        az = fmaf(z3, n3, az); aw = fmaf(w3, n3, aw);
    }
    for (; e < end; e++) {
        int2 c0 = g_csr[e];
        float n0 = __int_as_float(c0.y);
        float x0, y0, z0, w0;
        ldhf4(g_hf + (size_t)c0.x * D + lane * 4, x0, y0, z0, w0);
        ax = fmaf(x0, n0, ax); ay = fmaf(y0, n0, ay);
        az = fmaf(z0, n0, az); aw = fmaf(w0, n0, aw);
    }

    if (RELU) {
        ax = fmaxf(ax, 0.f); ay = fmaxf(ay, 0.f);
        az = fmaxf(az, 0.f); aw = fmaxf(aw, 0.f);
    }
    uint32_t h01, l01, h23, l23;
    split2(ax, ay, h01, l01);
    split2(az, aw, h23, l23);
    size_t base = (size_t)node * D + lane * 4;
    *(uint2*)(g_ahi + base) = make_uint2(h01, h23);
    *(uint2*)(g_alo + base) = make_uint2(l01, l23);
}

// ---------------- host launcher ----------------------------------------------
extern "C" void kernel_launch(void* const* d_in, const int* in_sizes, int n_in,
                              void* d_out, int out_size) {
    const float* x  = (const float*)d_in[0];
    const void*  ei = d_in[1];
    const float* ew = (const float*)d_in[2];
    const float* W1 = (const float*)d_in[3];
    const float* b1 = (const float*)d_in[4];
    const float* W2 = (const float*)d_in[5];
    const float* b2 = (const float*)d_in[6];
    const float* W3 = (const float*)d_in[7];
    const float* b3 = (const float*)d_in[8];
    const float* Wl = (const float*)d_in[9];
    const float* bl = (const float*)d_in[10];
    float* out = (float*)d_out;

    const int N = in_sizes[0] / D;
    const int E = in_sizes[2];

    unsigned short *whi = nullptr, *wlo = nullptr;
    cudaGetSymbolAddress((void**)&whi, g_whi);
    cudaGetSymbolAddress((void**)&wlo, g_wlo);

    cudaFuncSetAttribute(k_tgemm<0, 0>, cudaFuncAttributeMaxDynamicSharedMemorySize, SM_TOTAL);
    cudaFuncSetAttribute(k_tgemm<1, 0>, cudaFuncAttributeMaxDynamicSharedMemorySize, SM_TOTAL);
    cudaFuncSetAttribute(k_tgemm<1, 1>, cudaFuncAttributeMaxDynamicSharedMemorySize, SM_TOTAL);

    static cudaStream_t s_side = nullptr;
    static cudaEvent_t  s_fork = nullptr, s_join = nullptr;
    if (!s_side) {
        cudaStreamCreateWithFlags(&s_side, cudaStreamNonBlocking);
        cudaEventCreateWithFlags(&s_fork, cudaEventDisableTiming);
        cudaEventCreateWithFlags(&s_join, cudaEventDisableTiming);
    }

    const int T  = 256;
    const int gE = (E + T - 1) / T;
    const int gG = (N + TM - 1) / TM;
    const int gA = (N * 32 + T - 1) / T;
    const int nb = (N + SCAN_B - 1) / SCAN_B;

    // --- fork: side does weight split + layer-1 GEMM (no edge deps) ---
    cudaEventRecord(s_fork, 0);
    cudaStreamWaitEvent(s_side, s_fork, 0);
    k_wsplit<<<64, dim3(32, 8), 0, s_side>>>(W1, W2, W3, Wl);
    k_tgemm<0, 0><<<gG, T, SM_TOTAL, s_side>>>(x, whi, wlo, nullptr, nullptr, N);
    cudaEventRecord(s_join, s_side);

    // --- main: edge prep chain (concurrent with side) ---
    k_deg_accum<<<gE, T>>>(ei, ew, E, N);
    k_scan1    <<<nb, SCAN_B>>>(N);
    k_scan3    <<<nb, SCAN_B>>>(N, E, nb);
    k_fill     <<<gE, T>>>(ei, ew, E, N);
    cudaStreamWaitEvent(0, s_join, 0);

    // --- layer 1: agg (+b1, relu, split) -> gemm2 ---
    k_agg<true><<<gA, T>>>(b1, N);
    k_tgemm<1, 0><<<gG, T, SM_TOTAL>>>(nullptr, whi + 16384, wlo + 16384, nullptr, nullptr, N);
    // --- layer 2 ---
    k_agg<true><<<gA, T>>>(b2, N);
    k_tgemm<1, 0><<<gG, T, SM_TOTAL>>>(nullptr, whi + 2 * 16384, wlo + 2 * 16384, nullptr, nullptr, N);
    // --- layer 3 (no relu) ---
    k_agg<false><<<gA, T>>>(b3, N);
    // --- final linear ---
    k_tgemm<1, 1><<<gG, T, SM_TOTAL>>>(nullptr, whi + 3 * 16384, wlo + 3 * 16384, bl, out, N);
}

// round 15
// speedup vs baseline: 1.1593x; 1.0153x over previous
#include <cuda_runtime.h>
#include <cuda_bf16.h>
#include <cuda_fp16.h>
#include <cstdint>

#define NN 50000
#define NE 800000
#define D  128
#define SCAN_B 256
#define TM 128

#define LDS_STRIDE_B 144
#define AHI_OFF 0
#define ALO_OFF 18432
#define BHI_OFF 36864
#define BLO_OFF 55296
#define SM_TOTAL 73728

#define DEG_SCALE 4194304.0f

// ---------------- scratch (static device globals; no allocation) -------------
__device__ __half g_hf [NN * D];             // GEMM output (fp16 messages)
__device__ unsigned short g_ahi[NN * D];     // agg output, bf16 hi (relu'd)
__device__ unsigned short g_alo[NN * D];     // agg output, bf16 lo
__device__ int   g_eidx[NE];                 // within-row slot for each edge
__device__ unsigned long long g_pack[NN];    // zero-init; scan1 restores to 0
__device__ float g_dinv[NN];
// CSR (by dst)
__device__ int   g_rowtmp[NN];
__device__ int   g_rowptr[NN + 1];
__device__ int   g_bsum  [SCAN_B];
__device__ int2  g_csr   [NE];               // .x = src, .y = bitcast(norm)
// pre-split transposed weights
__device__ unsigned short g_whi[4 * 16384];
__device__ unsigned short g_wlo[4 * 16384];

// ---------------- helpers ------------------------------------------------------
__device__ __forceinline__ uint32_t smem_u32(const void* p) {
    uint32_t a;
    asm("{ .reg .u64 t; cvta.to.shared.u64 t, %1; cvt.u32.u64 %0, t; }" : "=r"(a) : "l"(p));
    return a;
}

__device__ __forceinline__ void ldmx4(uint32_t& r0, uint32_t& r1, uint32_t& r2,
                                      uint32_t& r3, uint32_t addr) {
    asm volatile("ldmatrix.sync.aligned.m8n8.x4.shared.b16 {%0,%1,%2,%3}, [%4];"
                 : "=r"(r0), "=r"(r1), "=r"(r2), "=r"(r3) : "r"(addr));
}

__device__ __forceinline__ void mma_bf16(float& c0, float& c1, float& c2, float& c3,
                                         uint32_t a0, uint32_t a1, uint32_t a2, uint32_t a3,
                                         uint32_t b0, uint32_t b1) {
    asm volatile("mma.sync.aligned.m16n8k16.row.col.f32.bf16.bf16.f32 "
                 "{%0,%1,%2,%3}, {%4,%5,%6,%7}, {%8,%9}, {%0,%1,%2,%3};"
                 : "+f"(c0), "+f"(c1), "+f"(c2), "+f"(c3)
                 : "r"(a0), "r"(a1), "r"(a2), "r"(a3), "r"(b0), "r"(b1));
}

__device__ __forceinline__ void split2(float x, float y, uint32_t& hi, uint32_t& lo) {
    __nv_bfloat16 hx = __float2bfloat16(x), hy = __float2bfloat16(y);
    __nv_bfloat16 lx = __float2bfloat16(x - __bfloat162float(hx));
    __nv_bfloat16 ly = __float2bfloat16(y - __bfloat162float(hy));
    hi = (uint32_t)__bfloat16_as_ushort(hx) | ((uint32_t)__bfloat16_as_ushort(hy) << 16);
    lo = (uint32_t)__bfloat16_as_ushort(lx) | ((uint32_t)__bfloat16_as_ushort(ly) << 16);
}

// widen uint4 (8 fp16) into 8 floats
__device__ __forceinline__ void h8_to_f(const uint4& r, float* f) {
    __half2 h;
    h = *reinterpret_cast<const __half2*>(&r.x); float2 a = __half22float2(h); f[0] = a.x; f[1] = a.y;
    h = *reinterpret_cast<const __half2*>(&r.y); float2 b = __half22float2(h); f[2] = b.x; f[3] = b.y;
    h = *reinterpret_cast<const __half2*>(&r.z); float2 c = __half22float2(h); f[4] = c.x; f[5] = c.y;
    h = *reinterpret_cast<const __half2*>(&r.w); float2 d = __half22float2(h); f[6] = d.x; f[7] = d.y;
}

// decode edge e (src,dst); is64 flag from per-block probe
__device__ __forceinline__ void decode_edge(const void* ei_raw, int is64, int e,
                                            int E, int n, int& s, int& d) {
    if (is64) {
        const long long* ei = (const long long*)ei_raw;
        s = (int)ei[e]; d = (int)ei[E + e];
    } else {
        const int* ei = (const int*)ei_raw;
        s = ei[e]; d = ei[E + e];
    }
    if ((unsigned)s >= (unsigned)n) s = 0;
    if ((unsigned)d >= (unsigned)n) d = 0;
}

__device__ __forceinline__ int probe_is64(const void* ei_raw) {
    __shared__ int s_nz;
    if (threadIdx.x == 0) s_nz = 0;
    __syncthreads();
    if (threadIdx.x < 64) {
        if (((const int*)ei_raw)[2 * threadIdx.x + 1] != 0) s_nz = 1;  // benign race
    }
    __syncthreads();
    return (s_nz == 0);
}

// ---------------- weight pre-split (side stream; no edge deps) ----------------
__global__ void k_wsplit(const float* __restrict__ W0, const float* __restrict__ W1,
                         const float* __restrict__ W2, const float* __restrict__ W3) {
    __shared__ float tile[32][33];
    const int b  = blockIdx.x;
    const int w  = b >> 4;
    const int k0 = ((b >> 2) & 3) * 32;
    const int n0 = (b & 3) * 32;
    const float* W = (w == 0) ? W0 : (w == 1) ? W1 : (w == 2) ? W2 : W3;
    const int tx = threadIdx.x, ty = threadIdx.y;
#pragma unroll
    for (int i = 0; i < 4; i++)
        tile[ty + 8 * i][tx] = W[(size_t)(k0 + ty + 8 * i) * D + n0 + tx];
    __syncthreads();
#pragma unroll
    for (int i = 0; i < 4; i++) {
        float v = tile[tx][ty + 8 * i];
        __nv_bfloat16 h = __float2bfloat16(v);
        __nv_bfloat16 l = __float2bfloat16(v - __bfloat162float(h));
        size_t idx = (size_t)w * 16384 + (size_t)(n0 + ty + 8 * i) * D + k0 + tx;
        g_whi[idx] = __bfloat16_as_ushort(h);
        g_wlo[idx] = __bfloat16_as_ushort(l);
    }
}

// ---------------- tensor-core GEMM --------------------------------------------
// AMODE 0: A from fp32 `in` (split in-kernel). AMODE 1: A from g_ahi/g_alo.
// OMODE 0: write fp16 to g_hf (no bias). OMODE 1: write fp32 to out (+bias).
template <int AMODE, int OMODE>
__global__ void __launch_bounds__(256)
k_tgemm(const float* __restrict__ in, const unsigned short* __restrict__ whi,
        const unsigned short* __restrict__ wlo,
        const float* __restrict__ bias, float* __restrict__ out, int n) {
    extern __shared__ char smem[];
    const uint32_t sb  = smem_u32(smem);
    const int tid   = threadIdx.x;
    const int wid   = tid >> 5;
    const int lane  = tid & 31;
    const int rbase = blockIdx.x * TM;

    const int m0 = wid * 16;
    const int rowInA = (lane & 7) + ((lane >> 3) & 1) * 8;
    const int kAddA  = (lane >> 4) * 8;
    const uint32_t aOffBytes = (uint32_t)((m0 + rowInA) * LDS_STRIDE_B + kAddA * 2);
    const int rowInB = (lane & 7) + (lane >> 4) * 8;
    const int kAddB  = ((lane >> 3) & 1) * 8;
    const uint32_t bOffBytes = (uint32_t)(rowInB * LDS_STRIDE_B + kAddB * 2);

    float acc[16][4];
#pragma unroll
    for (int t = 0; t < 16; t++) {
        acc[t][0] = 0.f; acc[t][1] = 0.f; acc[t][2] = 0.f; acc[t][3] = 0.f;
    }

    const int fillRow = tid >> 1;
    const int fillSub = (tid & 1) * 32;

#pragma unroll
    for (int stage = 0; stage < 2; stage++) {
        const int kstage = stage * 64;
        // ---- A fill ----
        {
            const int r = rbase + fillRow;
            char* ah = smem + AHI_OFF + fillRow * LDS_STRIDE_B + fillSub * 2;
            char* al = smem + ALO_OFF + fillRow * LDS_STRIDE_B + fillSub * 2;
            if (AMODE == 0) {
                const float4* src = (const float4*)(in + (size_t)r * D + kstage + fillSub);
#pragma unroll
                for (int k4 = 0; k4 < 8; k4++) {
                    float4 v = (r < n) ? src[k4] : make_float4(0.f, 0.f, 0.f, 0.f);
                    uint32_t h01, l01, h23, l23;
                    split2(v.x, v.y, h01, l01);
                    split2(v.z, v.w, h23, l23);
                    *(uint32_t*)(ah + k4 * 8)     = h01;
                    *(uint32_t*)(ah + k4 * 8 + 4) = h23;
                    *(uint32_t*)(al + k4 * 8)     = l01;
                    *(uint32_t*)(al + k4 * 8 + 4) = l23;
                }
            } else {
                const uint4* sh = (const uint4*)(g_ahi + (size_t)r * D + kstage + fillSub);
                const uint4* sl = (const uint4*)(g_alo + (size_t)r * D + kstage + fillSub);
                if (r < n) {
#pragma unroll
                    for (int q = 0; q < 4; q++) {
                        ((uint4*)ah)[q] = sh[q];
                        ((uint4*)al)[q] = sl[q];
                    }
                } else {
                    uint4 z = make_uint4(0, 0, 0, 0);
#pragma unroll
                    for (int q = 0; q < 4; q++) { ((uint4*)ah)[q] = z; ((uint4*)al)[q] = z; }
                }
            }
        }
        // ---- B fill: uint4 copies from pre-split weights ----
        {
            const int nn = fillRow;
            const uint4* sh = (const uint4*)(whi + (size_t)nn * D + kstage + fillSub);
            const uint4* sl = (const uint4*)(wlo + (size_t)nn * D + kstage + fillSub);
            uint4* bh = (uint4*)(smem + BHI_OFF + nn * LDS_STRIDE_B + fillSub * 2);
            uint4* bl = (uint4*)(smem + BLO_OFF + nn * LDS_STRIDE_B + fillSub * 2);
#pragma unroll
            for (int q = 0; q < 4; q++) { bh[q] = sh[q]; bl[q] = sl[q]; }
        }
        __syncthreads();

#pragma unroll
        for (int ks = 0; ks < 4; ks++) {
            const uint32_t kb = (uint32_t)(ks * 32);
            uint32_t ah0, ah1, ah2, ah3, al0, al1, al2, al3;
            ldmx4(ah0, ah1, ah2, ah3, sb + AHI_OFF + aOffBytes + kb);
            ldmx4(al0, al1, al2, al3, sb + ALO_OFF + aOffBytes + kb);
#pragma unroll
            for (int nc = 0; nc < 8; nc++) {
                const uint32_t bAddr = bOffBytes + (uint32_t)(nc * 16 * LDS_STRIDE_B) + kb;
                uint32_t bh0, bh1, bh2, bh3, bl0, bl1, bl2, bl3;
                ldmx4(bh0, bh1, bh2, bh3, sb + BHI_OFF + bAddr);
                ldmx4(bl0, bl1, bl2, bl3, sb + BLO_OFF + bAddr);
                float* c0 = acc[nc * 2];
                float* c1 = acc[nc * 2 + 1];
                mma_bf16(c0[0], c0[1], c0[2], c0[3], ah0, ah1, ah2, ah3, bh0, bh1);
                mma_bf16(c0[0], c0[1], c0[2], c0[3], ah0, ah1, ah2, ah3, bl0, bl1);
                mma_bf16(c0[0], c0[1], c0[2], c0[3], al0, al1, al2, al3, bh0, bh1);
                mma_bf16(c1[0], c1[1], c1[2], c1[3], ah0, ah1, ah2, ah3, bh2, bh3);
                mma_bf16(c1[0], c1[1], c1[2], c1[3], ah0, ah1, ah2, ah3, bl2, bl3);
                mma_bf16(c1[0], c1[1], c1[2], c1[3], al0, al1, al2, al3, bh2, bh3);
            }
        }
        __syncthreads();
    }

    const int rTop = rbase + m0 + (lane >> 2);
    const int cOff = (lane & 3) * 2;
#pragma unroll
    for (int t = 0; t < 16; t++) {
        const int col = t * 8 + cOff;
        if (OMODE == 0) {
            if (rTop < n) {
                __half2 v = __floats2half2_rn(acc[t][0], acc[t][1]);
                *(__half2*)(g_hf + (size_t)rTop * D + col) = v;
            }
            if (rTop + 8 < n) {
                __half2 v = __floats2half2_rn(acc[t][2], acc[t][3]);
                *(__half2*)(g_hf + (size_t)(rTop + 8) * D + col) = v;
            }
        } else {
            float bx = bias[col], by = bias[col + 1];
            if (rTop < n) {
                float2 v = make_float2(acc[t][0] + bx, acc[t][1] + by);
                *(float2*)(out + (size_t)rTop * D + col) = v;
            }
            if (rTop + 8 < n) {
                float2 v = make_float2(acc[t][2] + bx, acc[t][3] + by);
                *(float2*)(out + (size_t)(rTop + 8) * D + col) = v;
            }
        }
    }
}

// ---------------- degree+count accumulation ------------------------------------
__global__ void k_deg_accum(const void* __restrict__ ei_raw,
                            const float* __restrict__ w, int E, int n) {
    const int is64 = probe_is64(ei_raw);
    int e = blockIdx.x * blockDim.x + threadIdx.x;
    if (e >= E) return;
    int s, d;
    decode_edge(ei_raw, is64, e, E, n, s, d);
    unsigned long long inc = (1ull << 32) |
        (unsigned long long)(unsigned)__float2uint_rn(w[e] * DEG_SCALE);
    unsigned long long old = atomicAdd(&g_pack[d], inc);
    g_eidx[e] = (int)(old >> 32);
}

// ---------------- CSR scan pass 1 (also dinv + g_pack reset) -------------------
__global__ void k_scan1(int n) {
    __shared__ int sh[SCAN_B];
    int i = blockIdx.x * SCAN_B + threadIdx.x;
    int v = 0;
    if (i < n) {
        unsigned long long p = g_pack[i];
        g_pack[i] = 0ull;                       // restore for next graph replay
        v = (int)(p >> 32);
        float deg = 1.0f + (float)(unsigned)(p & 0xFFFFFFFFull) * (1.0f / DEG_SCALE);
        g_dinv[i] = rsqrtf(deg);
    }
    sh[threadIdx.x] = v;
    __syncthreads();
    for (int o = 1; o < SCAN_B; o <<= 1) {
        int t = (threadIdx.x >= o) ? sh[threadIdx.x - o] : 0;
        __syncthreads();
        sh[threadIdx.x] += t;
        __syncthreads();
    }
    if (i < n) g_rowtmp[i] = sh[threadIdx.x] - v;
    if (threadIdx.x == SCAN_B - 1) g_bsum[blockIdx.x] = sh[SCAN_B - 1];
}

// ---------------- CSR scan pass 2: per-block reduce of prior block sums --------
__global__ void k_scan3(int n, int E, int nb) {
    __shared__ int red[SCAN_B];
    const int b = blockIdx.x;
    int part = (threadIdx.x < b && threadIdx.x < nb) ? g_bsum[threadIdx.x] : 0;
    red[threadIdx.x] = part;
    __syncthreads();
    for (int o = SCAN_B / 2; o > 0; o >>= 1) {
        if (threadIdx.x < o) red[threadIdx.x] += red[threadIdx.x + o];
        __syncthreads();
    }
    int boff = red[0];
    int i = b * SCAN_B + threadIdx.x;
    if (i < n) g_rowptr[i] = g_rowtmp[i] + boff;
    if (i == 0) g_rowptr[n] = E;
}

// ---------------- fill: csr = (src, nrm); re-decodes edge_index ----------------
__global__ void k_fill(const void* __restrict__ ei_raw,
                       const float* __restrict__ w, int E, int n) {
    const int is64 = probe_is64(ei_raw);
    int e = blockIdx.x * blockDim.x + threadIdx.x;
    if (e >= E) return;
    int s, d;
    decode_edge(ei_raw, is64, e, E, n, s, d);
    int pos = g_rowptr[d] + g_eidx[e];
    float nrm = g_dinv[s] * w[e] * g_dinv[d];
    int2 v;
    v.x = s;
    v.y = __float_as_int(nrm);
    g_csr[pos] = v;
}

// ---------------- fused aggregation: dual-edge half-warp, uint4 gathers -------
// warp per node; half h processes edges at offsets h, h+2, h+4, ... (unroll 2)
// lane handles 8 fp16 columns (lane16*8 .. +7); final shfl_xor(16) combine.
template <bool RELU>
__global__ void __launch_bounds__(256)
k_agg(const float* __restrict__ bias, int n) {
    int node   = (blockIdx.x * blockDim.x + threadIdx.x) >> 5;
    int lane   = threadIdx.x & 31;
    int half   = lane >> 4;
    int lane16 = lane & 15;
    if (node >= n) return;

    const int beg = g_rowptr[node];
    const int end = g_rowptr[node + 1];
    const int colB = lane16 * 8;                // first of 8 columns

    float acc[8];
    if (half == 0) {
        // self term + bias
        float di = g_dinv[node];
        float s  = di * di;
        uint4 r = *(const uint4*)(g_hf + (size_t)node * D + colB);
        float f[8];
        h8_to_f(r, f);
        const float4 b0 = *(const float4*)(bias + colB);
        const float4 b1 = *(const float4*)(bias + colB + 4);
        acc[0] = fmaf(f[0], s, b0.x); acc[1] = fmaf(f[1], s, b0.y);
        acc[2] = fmaf(f[2], s, b0.z); acc[3] = fmaf(f[3], s, b0.w);
        acc[4] = fmaf(f[4], s, b1.x); acc[5] = fmaf(f[5], s, b1.y);
        acc[6] = fmaf(f[6], s, b1.z); acc[7] = fmaf(f[7], s, b1.w);
    } else {
#pragma unroll
        for (int i = 0; i < 8; i++) acc[i] = 0.f;
    }

    int e = beg + half;
    // unroll 2: edges e and e+2 for this half
    for (; e + 2 < end; e += 4) {
        int2 c0 = g_csr[e];
        int2 c1 = g_csr[e + 2];
        uint4 r0 = *(const uint4*)(g_hf + (size_t)c0.x * D + colB);
        uint4 r1 = *(const uint4*)(g_hf + (size_t)c1.x * D + colB);
        float n0 = __int_as_float(c0.y);
        float n1 = __int_as_float(c1.y);
        float f0[8], f1[8];
        h8_to_f(r0, f0);
        h8_to_f(r1, f1);
#pragma unroll
        for (int i = 0; i < 8; i++) acc[i] = fmaf(f0[i], n0, acc[i]);
#pragma unroll
        for (int i = 0; i < 8; i++) acc[i] = fmaf(f1[i], n1, acc[i]);
    }
    for (; e < end; e += 2) {
        int2 c0 = g_csr[e];
        uint4 r0 = *(const uint4*)(g_hf + (size_t)c0.x * D + colB);
        float n0 = __int_as_float(c0.y);
        float f0[8];
        h8_to_f(r0, f0);
#pragma unroll
        for (int i = 0; i < 8; i++) acc[i] = fmaf(f0[i], n0, acc[i]);
    }

    // combine the two halves (whole warp alive: node uniform across warp)
#pragma unroll
    for (int i = 0; i < 8; i++)
        acc[i] += __shfl_xor_sync(0xFFFFFFFFu, acc[i], 16);

    if (RELU) {
#pragma unroll
        for (int i = 0; i < 8; i++) acc[i] = fmaxf(acc[i], 0.f);
    }

    // split into bf16 hi/lo; half 0 stores hi uint4, half 1 stores lo uint4
    uint32_t h01, l01, h23, l23, h45, l45, h67, l67;
    split2(acc[0], acc[1], h01, l01);
    split2(acc[2], acc[3], h23, l23);
    split2(acc[4], acc[5], h45, l45);
    split2(acc[6], acc[7], h67, l67);
    size_t base = (size_t)node * D + colB;
    if (half == 0)
        *(uint4*)(g_ahi + base) = make_uint4(h01, h23, h45, h67);
    else
        *(uint4*)(g_alo + base) = make_uint4(l01, l23, l45, l67);
}

// ---------------- host launcher ----------------------------------------------
extern "C" void kernel_launch(void* const* d_in, const int* in_sizes, int n_in,
                              void* d_out, int out_size) {
    const float* x  = (const float*)d_in[0];
    const void*  ei = d_in[1];
    const float* ew = (const float*)d_in[2];
    const float* W1 = (const float*)d_in[3];
    const float* b1 = (const float*)d_in[4];
    const float* W2 = (const float*)d_in[5];
    const float* b2 = (const float*)d_in[6];
    const float* W3 = (const float*)d_in[7];
    const float* b3 = (const float*)d_in[8];
    const float* Wl = (const float*)d_in[9];
    const float* bl = (const float*)d_in[10];
    float* out = (float*)d_out;

    const int N = in_sizes[0] / D;
    const int E = in_sizes[2];

    unsigned short *whi = nullptr, *wlo = nullptr;
    cudaGetSymbolAddress((void**)&whi, g_whi);
    cudaGetSymbolAddress((void**)&wlo, g_wlo);

    cudaFuncSetAttribute(k_tgemm<0, 0>, cudaFuncAttributeMaxDynamicSharedMemorySize, SM_TOTAL);
    cudaFuncSetAttribute(k_tgemm<1, 0>, cudaFuncAttributeMaxDynamicSharedMemorySize, SM_TOTAL);
    cudaFuncSetAttribute(k_tgemm<1, 1>, cudaFuncAttributeMaxDynamicSharedMemorySize, SM_TOTAL);

    static cudaStream_t s_side = nullptr;
    static cudaEvent_t  s_fork = nullptr, s_join = nullptr;
    if (!s_side) {
        cudaStreamCreateWithFlags(&s_side, cudaStreamNonBlocking);
        cudaEventCreateWithFlags(&s_fork, cudaEventDisableTiming);
        cudaEventCreateWithFlags(&s_join, cudaEventDisableTiming);
    }

    const int T  = 256;
    const int gE = (E + T - 1) / T;
    const int gG = (N + TM - 1) / TM;
    const int gA = (N * 32 + T - 1) / T;
    const int nb = (N + SCAN_B - 1) / SCAN_B;

    // --- fork: side does weight split + layer-1 GEMM (no edge deps) ---
    cudaEventRecord(s_fork, 0);
    cudaStreamWaitEvent(s_side, s_fork, 0);
    k_wsplit<<<64, dim3(32, 8), 0, s_side>>>(W1, W2, W3, Wl);
    k_tgemm<0, 0><<<gG, T, SM_TOTAL, s_side>>>(x, whi, wlo, nullptr, nullptr, N);
    cudaEventRecord(s_join, s_side);

    // --- main: edge prep chain (concurrent with side) ---
    k_deg_accum<<<gE, T>>>(ei, ew, E, N);
    k_scan1    <<<nb, SCAN_B>>>(N);
    k_scan3    <<<nb, SCAN_B>>>(N, E, nb);
    k_fill     <<<gE, T>>>(ei, ew, E, N);
    cudaStreamWaitEvent(0, s_join, 0);

    // --- layer 1: agg (+b1, relu, split) -> gemm2 ---
    k_agg<true><<<gA, T>>>(b1, N);
    k_tgemm<1, 0><<<gG, T, SM_TOTAL>>>(nullptr, whi + 16384, wlo + 16384, nullptr, nullptr, N);
    // --- layer 2 ---
    k_agg<true><<<gA, T>>>(b2, N);
    k_tgemm<1, 0><<<gG, T, SM_TOTAL>>>(nullptr, whi + 2 * 16384, wlo + 2 * 16384, nullptr, nullptr, N);
    // --- layer 3 (no relu) ---
    k_agg<false><<<gA, T>>>(b3, N);
    // --- final linear ---
    k_tgemm<1, 1><<<gG, T, SM_TOTAL>>>(nullptr, whi + 3 * 16384, wlo + 3 * 16384, bl, out, N);
}